// round 1
// baseline (speedup 1.0000x reference)
#include <cuda_runtime.h>
#include <math.h>

#define B_    32
#define CIN   96
#define COUT  96
#define HID   576
#define E_    8
#define HW    3136
#define WD    56
#define EPS   1e-5f

// ---------------- scratch (device globals; no allocation) ----------------
__device__ float g_y   [(size_t)B_*HID*HW];   // expanded activations (post BN1+ReLU6)
__device__ float g_y2  [(size_t)B_*HID*HW];   // after depthwise (post BN2+ReLU6)
__device__ float g_xpool[B_*CIN];
__device__ float g_ypool[B_*HID];             // sum of y over HW (div by HW later)
__device__ float g_r1  [B_*E_];
__device__ float g_rblk[B_*E_];
__device__ float g_w1c [(size_t)B_*HID*CIN];  // mixed expand weights
__device__ float g_w3c [(size_t)B_*COUT*HID]; // mixed project weights
__device__ float g_kw  [B_*HID*9];            // mixed depthwise kernels

// ---------------- small kernels ----------------
__global__ void k_zero_ypool() {
    int i = blockIdx.x * 256 + threadIdx.x;
    if (i < B_ * HID) g_ypool[i] = 0.0f;
}

__global__ void k_xpool(const float* __restrict__ x) {
    int bc = blockIdx.x;                       // 0..B_*CIN-1
    const float* p = x + (size_t)bc * HW;
    float s = 0.0f;
    for (int i = threadIdx.x; i < HW; i += 256) s += p[i];
    __shared__ float sm[256];
    sm[threadIdx.x] = s; __syncthreads();
    for (int o = 128; o > 0; o >>= 1) {
        if (threadIdx.x < o) sm[threadIdx.x] += sm[threadIdx.x + o];
        __syncthreads();
    }
    if (threadIdx.x == 0) g_xpool[bc] = sm[0] * (1.0f / HW);
}

__global__ void k_route1(const float* __restrict__ wr1, const float* __restrict__ br1,
                         const float* __restrict__ wr3, const float* __restrict__ br3) {
    int t = threadIdx.x;          // 256 threads = 32 b * 8 e
    int b = t >> 3, e = t & 7;
    const float* xp = g_xpool + b * CIN;
    float s1 = br1[e], s3 = br3[e];
    #pragma unroll 4
    for (int c = 0; c < CIN; c++) {
        float xv = xp[c];
        s1 += xv * wr1[e * CIN + c];
        s3 += xv * wr3[e * CIN + c];
    }
    g_r1[t]   = 1.0f / (1.0f + expf(-s1));
    g_rblk[t] = 1.0f / (1.0f + expf(-s3));
}

__global__ void k_mix1(const float* __restrict__ w1) {
    int b = blockIdx.y;
    int i = blockIdx.x * 256 + threadIdx.x;    // < HID*CIN = 55296
    if (i >= HID * CIN) return;
    const float* r = g_r1 + b * E_;
    float s = 0.0f;
    #pragma unroll
    for (int e = 0; e < E_; e++) s += r[e] * w1[(size_t)e * HID * CIN + i];
    g_w1c[(size_t)b * HID * CIN + i] = s;
}

__global__ void k_mix3(const float* __restrict__ w3) {
    int b = blockIdx.y;
    int i = blockIdx.x * 256 + threadIdx.x;    // < COUT*HID = 55296
    if (i >= COUT * HID) return;
    const float* r = g_rblk + b * E_;
    float s = 0.0f;
    #pragma unroll
    for (int e = 0; e < E_; e++) s += r[e] * w3[(size_t)e * COUT * HID + i];
    g_w3c[(size_t)b * COUT * HID + i] = s;
}

__global__ void k_route2(const float* __restrict__ wr2, const float* __restrict__ br2,
                         const float* __restrict__ w2) {
    int b = blockIdx.x;
    __shared__ float rs[E_];
    if (threadIdx.x < E_) {
        int e = threadIdx.x;
        float s = br2[e];
        const float* yp = g_ypool + b * HID;
        #pragma unroll 4
        for (int c = 0; c < HID; c++)
            s += (yp[c] * (1.0f / HW)) * wr2[e * HID + c];
        rs[e] = 1.0f / (1.0f + expf(-s));
    }
    __syncthreads();
    for (int i = threadIdx.x; i < HID * 9; i += 256) {
        float s = 0.0f;
        #pragma unroll
        for (int e = 0; e < E_; e++) s += rs[e] * w2[(size_t)e * HID * 9 + i];
        g_kw[b * HID * 9 + i] = s;
    }
}

// ---------------- expand GEMM: y[b,m,n] = sum_c w1c[b,m,c]*x[b,c,n]; BN1+ReLU6; ypool ----
// block tile: M=96 x N=64, K-chunk 32, 384 threads, 4x4 per thread
__global__ __launch_bounds__(384) void k_expand(const float* __restrict__ x,
        const float* __restrict__ g1, const float* __restrict__ bt1,
        const float* __restrict__ m1, const float* __restrict__ v1) {
    const int b = blockIdx.z, m0 = blockIdx.y * 96, n0 = blockIdx.x * 64;
    __shared__ float ws[96][33];   // [m][k]
    __shared__ float xs[32][68];   // [k][n], 16B-aligned rows for LDS.128
    __shared__ float psum[96];
    const int tid = threadIdx.x, tx = tid & 15, ty = tid >> 4;  // ty 0..23
    float acc[4][4] = {};
    const float* wmat = g_w1c + (size_t)b * HID * CIN;
    const float* xb   = x     + (size_t)b * CIN * HW;

    for (int k0 = 0; k0 < CIN; k0 += 32) {
        {
            int kk = tid & 31, mm = tid >> 5;          // mm 0..11
            #pragma unroll
            for (int r = 0; r < 8; r++)
                ws[mm + r * 12][kk] = wmat[(size_t)(m0 + mm + r * 12) * CIN + k0 + kk];
        }
        for (int idx = tid; idx < 2048; idx += 384) {
            int kk = idx >> 6, nn = idx & 63;
            xs[kk][nn] = xb[(size_t)(k0 + kk) * HW + n0 + nn];
        }
        __syncthreads();
        #pragma unroll
        for (int k = 0; k < 32; k++) {
            float a[4];
            #pragma unroll
            for (int i = 0; i < 4; i++) a[i] = ws[ty * 4 + i][k];
            float4 bv = *reinterpret_cast<const float4*>(&xs[k][tx * 4]);
            float bb[4] = {bv.x, bv.y, bv.z, bv.w};
            #pragma unroll
            for (int i = 0; i < 4; i++)
                #pragma unroll
                for (int j = 0; j < 4; j++)
                    acc[i][j] += a[i] * bb[j];
        }
        __syncthreads();
    }

    if (tid < 96) psum[tid] = 0.0f;
    __syncthreads();

    float* yb = g_y + (size_t)b * HID * HW;
    #pragma unroll
    for (int i = 0; i < 4; i++) {
        int m = m0 + ty * 4 + i;
        float sc = g1[m] * rsqrtf(v1[m] + EPS);
        float bi = bt1[m] - m1[m] * sc;
        float rsum = 0.0f;
        #pragma unroll
        for (int j = 0; j < 4; j++) {
            float v = acc[i][j] * sc + bi;
            v = fminf(fmaxf(v, 0.0f), 6.0f);
            yb[(size_t)m * HW + n0 + tx * 4 + j] = v;
            rsum += v;
        }
        atomicAdd(&psum[ty * 4 + i], rsum);
    }
    __syncthreads();
    if (tid < 96) atomicAdd(&g_ypool[b * HID + m0 + tid], psum[tid]);
}

// ---------------- depthwise 3x3 + BN2 + ReLU6 ----------------
__global__ void k_dw(const float* __restrict__ g2, const float* __restrict__ bt2,
                     const float* __restrict__ m2, const float* __restrict__ v2) {
    int bc = blockIdx.x;                 // b*HID + ch
    int ch = bc % HID;
    __shared__ float t[58 * 58];
    const float* yin = g_y + (size_t)bc * HW;
    for (int i = threadIdx.x; i < 58 * 58; i += 256) {
        int r = i / 58, c = i % 58;
        int gr = r - 1, gc = c - 1;
        t[i] = (gr >= 0 && gr < WD && gc >= 0 && gc < WD) ? yin[gr * WD + gc] : 0.0f;
    }
    const float* kp = g_kw + bc * 9;
    float w0 = kp[0], w1 = kp[1], w2 = kp[2],
          w3 = kp[3], w4 = kp[4], w5 = kp[5],
          w6 = kp[6], w7 = kp[7], w8 = kp[8];
    float sc = g2[ch] * rsqrtf(v2[ch] + EPS);
    float bi = bt2[ch] - m2[ch] * sc;
    __syncthreads();
    float* yout = g_y2 + (size_t)bc * HW;
    for (int p = threadIdx.x; p < HW; p += 256) {
        int r = p / WD, c = p % WD;
        const float* tp = &t[r * 58 + c];
        float s = tp[0]   * w0 + tp[1]   * w1 + tp[2]   * w2
                + tp[58]  * w3 + tp[59]  * w4 + tp[60]  * w5
                + tp[116] * w6 + tp[117] * w7 + tp[118] * w8;
        s = s * sc + bi;
        s = fminf(fmaxf(s, 0.0f), 6.0f);
        yout[p] = s;
    }
}

// ---------------- project GEMM: out[b,m,n] = BN3(sum_k w3c[b,m,k]*y2[b,k,n]) + x ----
__global__ __launch_bounds__(384) void k_proj(const float* __restrict__ x,
        float* __restrict__ out,
        const float* __restrict__ g3, const float* __restrict__ bt3,
        const float* __restrict__ m3, const float* __restrict__ v3) {
    const int b = blockIdx.y, n0 = blockIdx.x * 64;
    __shared__ float ws[96][33];
    __shared__ float xs[32][68];
    const int tid = threadIdx.x, tx = tid & 15, ty = tid >> 4;
    float acc[4][4] = {};
    const float* wmat = g_w3c + (size_t)b * COUT * HID;
    const float* yb   = g_y2  + (size_t)b * HID * HW;

    for (int k0 = 0; k0 < HID; k0 += 32) {
        {
            int kk = tid & 31, mm = tid >> 5;
            #pragma unroll
            for (int r = 0; r < 8; r++)
                ws[mm + r * 12][kk] = wmat[(size_t)(mm + r * 12) * HID + k0 + kk];
        }
        for (int idx = tid; idx < 2048; idx += 384) {
            int kk = idx >> 6, nn = idx & 63;
            xs[kk][nn] = yb[(size_t)(k0 + kk) * HW + n0 + nn];
        }
        __syncthreads();
        #pragma unroll
        for (int k = 0; k < 32; k++) {
            float a[4];
            #pragma unroll
            for (int i = 0; i < 4; i++) a[i] = ws[ty * 4 + i][k];
            float4 bv = *reinterpret_cast<const float4*>(&xs[k][tx * 4]);
            float bb[4] = {bv.x, bv.y, bv.z, bv.w};
            #pragma unroll
            for (int i = 0; i < 4; i++)
                #pragma unroll
                for (int j = 0; j < 4; j++)
                    acc[i][j] += a[i] * bb[j];
        }
        __syncthreads();
    }

    const float* xb = x + (size_t)b * CIN * HW;
    float* ob = out + (size_t)b * COUT * HW;
    #pragma unroll
    for (int i = 0; i < 4; i++) {
        int m = ty * 4 + i;
        float sc = g3[m] * rsqrtf(v3[m] + EPS);
        float bi = bt3[m] - m3[m] * sc;
        #pragma unroll
        for (int j = 0; j < 4; j++) {
            int n = n0 + tx * 4 + j;
            ob[(size_t)m * HW + n] = acc[i][j] * sc + bi + xb[(size_t)m * HW + n];
        }
    }
}

// ---------------- launcher ----------------
extern "C" void kernel_launch(void* const* d_in, const int* in_sizes, int n_in,
                              void* d_out, int out_size) {
    const float* x    = (const float*)d_in[0];
    const float* w_r1 = (const float*)d_in[1];
    const float* b_r1 = (const float*)d_in[2];
    const float* w1   = (const float*)d_in[3];
    const float* g1   = (const float*)d_in[4];
    const float* bt1  = (const float*)d_in[5];
    const float* m1   = (const float*)d_in[6];
    const float* v1   = (const float*)d_in[7];
    const float* w_r2 = (const float*)d_in[8];
    const float* b_r2 = (const float*)d_in[9];
    const float* w2   = (const float*)d_in[10];
    const float* g2   = (const float*)d_in[11];
    const float* bt2  = (const float*)d_in[12];
    const float* m2   = (const float*)d_in[13];
    const float* v2   = (const float*)d_in[14];
    const float* w3   = (const float*)d_in[15];
    const float* g3   = (const float*)d_in[16];
    const float* bt3  = (const float*)d_in[17];
    const float* m3   = (const float*)d_in[18];
    const float* v3   = (const float*)d_in[19];
    const float* w_r3 = (const float*)d_in[20];
    const float* b_r3 = (const float*)d_in[21];
    float* out = (float*)d_out;

    k_zero_ypool<<<(B_ * HID + 255) / 256, 256>>>();
    k_xpool<<<B_ * CIN, 256>>>(x);
    k_route1<<<1, 256>>>(w_r1, b_r1, w_r3, b_r3);
    k_mix1<<<dim3(216, B_), 256>>>(w1);
    k_mix3<<<dim3(216, B_), 256>>>(w3);
    k_expand<<<dim3(49, 6, B_), 384>>>(x, g1, bt1, m1, v1);
    k_route2<<<B_, 256>>>(w_r2, b_r2, w2);
    k_dw<<<B_ * HID, 256>>>(g2, bt2, m2, v2);
    k_proj<<<dim3(49, B_), 384>>>(x, out, g3, bt3, m3, v3);
}

// round 2
// speedup vs baseline: 1.5964x; 1.5964x over previous
#include <cuda_runtime.h>
#include <math.h>
#include <stdint.h>

#define B_    32
#define CIN   96
#define COUT  96
#define HID   576
#define E_    8
#define HW    3136
#define WD    56
#define EPS   1e-5f

// ---------------- scratch (device globals; no allocation) ----------------
__device__ float g_y   [(size_t)B_*HID*HW];   // expanded activations (post BN1+ReLU6), fp32
__device__ float g_y2  [(size_t)B_*HID*HW];   // after depthwise (post BN2+ReLU6), tf32-rounded
__device__ float g_xpool[B_*CIN];
__device__ float g_ypool[B_*HID];             // sum of y over HW
__device__ float g_r1  [B_*E_];
__device__ float g_rblk[B_*E_];
__device__ float g_w1t [(size_t)B_*CIN*HID];  // mixed expand weights, transposed [b][k=CIN][m=HID], tf32
__device__ float g_w3t [(size_t)B_*HID*COUT]; // mixed project weights, transposed [b][k=HID][m=COUT], tf32
__device__ float g_kw  [B_*HID*9];            // mixed depthwise kernels (fp32)

// ---------------- helpers ----------------
__device__ __forceinline__ float to_tf32(float x) {
    float r;
    asm("cvt.rna.tf32.f32 %0, %1;" : "=f"(r) : "f"(x));
    return r;
}

__device__ __forceinline__ void mma_tf32(float d[4], const uint32_t a[4], const uint32_t b[2]) {
    asm volatile(
        "mma.sync.aligned.m16n8k8.row.col.f32.tf32.tf32.f32 "
        "{%0,%1,%2,%3}, {%4,%5,%6,%7}, {%8,%9}, {%0,%1,%2,%3};"
        : "+f"(d[0]), "+f"(d[1]), "+f"(d[2]), "+f"(d[3])
        : "r"(a[0]), "r"(a[1]), "r"(a[2]), "r"(a[3]), "r"(b[0]), "r"(b[1]));
}

__device__ __forceinline__ uint32_t fbits(float x) { return __float_as_uint(x); }

// ---------------- small kernels ----------------
__global__ void k_zero_ypool() {
    int i = blockIdx.x * 256 + threadIdx.x;
    if (i < B_ * HID) g_ypool[i] = 0.0f;
}

__global__ void k_xpool(const float* __restrict__ x) {
    int bc = blockIdx.x;
    const float* p = x + (size_t)bc * HW;
    float s = 0.0f;
    for (int i = threadIdx.x; i < HW; i += 256) s += p[i];
    __shared__ float sm[256];
    sm[threadIdx.x] = s; __syncthreads();
    for (int o = 128; o > 0; o >>= 1) {
        if (threadIdx.x < o) sm[threadIdx.x] += sm[threadIdx.x + o];
        __syncthreads();
    }
    if (threadIdx.x == 0) g_xpool[bc] = sm[0] * (1.0f / HW);
}

__global__ void k_route1(const float* __restrict__ wr1, const float* __restrict__ br1,
                         const float* __restrict__ wr3, const float* __restrict__ br3) {
    int t = threadIdx.x;          // 256 threads = 32 b * 8 e
    int b = t >> 3, e = t & 7;
    const float* xp = g_xpool + b * CIN;
    float s1 = br1[e], s3 = br3[e];
    #pragma unroll 4
    for (int c = 0; c < CIN; c++) {
        float xv = xp[c];
        s1 += xv * wr1[e * CIN + c];
        s3 += xv * wr3[e * CIN + c];
    }
    g_r1[t]   = 1.0f / (1.0f + expf(-s1));
    g_rblk[t] = 1.0f / (1.0f + expf(-s3));
}

// mix + transpose + tf32-round for expand weights:  w1[E][HID][CIN] -> g_w1t[b][CIN][HID]
__global__ void k_mix1(const float* __restrict__ w1) {
    int b = blockIdx.z, m0 = blockIdx.y * 32, k0 = blockIdx.x * 32;
    __shared__ float sm[32][33];
    __shared__ float rs[E_];
    int tid = threadIdx.x, tx = tid & 31, ty = tid >> 5;
    if (tid < E_) rs[tid] = g_r1[b * E_ + tid];
    __syncthreads();
    #pragma unroll
    for (int j = 0; j < 4; j++) {
        int m = m0 + ty + j * 8, k = k0 + tx;
        float s = 0.0f;
        #pragma unroll
        for (int e = 0; e < E_; e++) s += rs[e] * w1[((size_t)e * HID + m) * CIN + k];
        sm[ty + j * 8][tx] = to_tf32(s);
    }
    __syncthreads();
    #pragma unroll
    for (int j = 0; j < 4; j++) {
        int kk = ty + j * 8;
        g_w1t[(size_t)b * CIN * HID + (size_t)(k0 + kk) * HID + m0 + tx] = sm[tx][kk];
    }
}

// mix + transpose + tf32-round for project weights: w3[E][COUT][HID] -> g_w3t[b][HID][COUT]
__global__ void k_mix3(const float* __restrict__ w3) {
    int b = blockIdx.z, m0 = blockIdx.y * 32, k0 = blockIdx.x * 32;
    __shared__ float sm[32][33];
    __shared__ float rs[E_];
    int tid = threadIdx.x, tx = tid & 31, ty = tid >> 5;
    if (tid < E_) rs[tid] = g_rblk[b * E_ + tid];
    __syncthreads();
    #pragma unroll
    for (int j = 0; j < 4; j++) {
        int m = m0 + ty + j * 8, k = k0 + tx;
        float s = 0.0f;
        #pragma unroll
        for (int e = 0; e < E_; e++) s += rs[e] * w3[((size_t)e * COUT + m) * HID + k];
        sm[ty + j * 8][tx] = to_tf32(s);
    }
    __syncthreads();
    #pragma unroll
    for (int j = 0; j < 4; j++) {
        int kk = ty + j * 8;
        g_w3t[(size_t)b * HID * COUT + (size_t)(k0 + kk) * COUT + m0 + tx] = sm[tx][kk];
    }
}

__global__ void k_route2(const float* __restrict__ wr2, const float* __restrict__ br2,
                         const float* __restrict__ w2) {
    int b = blockIdx.x;
    __shared__ float rs[E_];
    if (threadIdx.x < E_) {
        int e = threadIdx.x;
        float s = br2[e];
        const float* yp = g_ypool + b * HID;
        #pragma unroll 4
        for (int c = 0; c < HID; c++)
            s += (yp[c] * (1.0f / HW)) * wr2[e * HID + c];
        rs[e] = 1.0f / (1.0f + expf(-s));
    }
    __syncthreads();
    for (int i = threadIdx.x; i < HID * 9; i += 256) {
        float s = 0.0f;
        #pragma unroll
        for (int e = 0; e < E_; e++) s += rs[e] * w2[(size_t)e * HID * 9 + i];
        g_kw[b * HID * 9 + i] = s;
    }
}

// ---------------- expand GEMM (tf32 tensor cores) ----------------
// y[b,m,n] = BN1/ReLU6( sum_k w1t[b,k,m] * x[b,k,n] ),  fused ypool reduction.
// block tile M=96 x N=128, K-chunk 32; 8 warps as 2(m) x 4(n); warp tile 48x32.
__global__ __launch_bounds__(256, 2) void k_expand(const float* __restrict__ x,
        const float* __restrict__ g1, const float* __restrict__ bt1,
        const float* __restrict__ m1, const float* __restrict__ v1) {
    const int b = blockIdx.z, m0 = blockIdx.y * 96, n0 = blockIdx.x * 128;
    __shared__ float As[32][104];   // [k][m] (tf32 values)
    __shared__ float Bs[32][136];   // [k][n] (tf32 values)
    __shared__ float psum[96];
    const int tid = threadIdx.x, lane = tid & 31, wid = tid >> 5;
    const int wm = wid >> 2, wn = wid & 3;
    const int gID = lane >> 2, tig = lane & 3;
    float acc[3][4][4];
    #pragma unroll
    for (int i = 0; i < 3; i++)
        #pragma unroll
        for (int j = 0; j < 4; j++)
            #pragma unroll
            for (int q = 0; q < 4; q++) acc[i][j][q] = 0.0f;

    const float* Ag = g_w1t + (size_t)b * CIN * HID;   // [k][m=HID]
    const float* Bg = x     + (size_t)b * CIN * HW;    // [k][n=HW]

    for (int k0 = 0; k0 < CIN; k0 += 32) {
        for (int i = tid; i < 32 * 96; i += 256) {
            int kk = i / 96, mm = i % 96;
            As[kk][mm] = Ag[(size_t)(k0 + kk) * HID + m0 + mm];
        }
        for (int i = tid; i < 32 * 128; i += 256) {
            int kk = i >> 7, nn = i & 127;
            int n = n0 + nn;
            Bs[kk][nn] = (n < HW) ? to_tf32(Bg[(size_t)(k0 + kk) * HW + n]) : 0.0f;
        }
        __syncthreads();
        #pragma unroll
        for (int ks = 0; ks < 4; ks++) {
            const int kb = ks * 8;
            uint32_t a[3][4], bb[4][2];
            #pragma unroll
            for (int mt = 0; mt < 3; mt++) {
                int row = wm * 48 + mt * 16 + gID;
                a[mt][0] = fbits(As[kb + tig][row]);
                a[mt][1] = fbits(As[kb + tig][row + 8]);
                a[mt][2] = fbits(As[kb + tig + 4][row]);
                a[mt][3] = fbits(As[kb + tig + 4][row + 8]);
            }
            #pragma unroll
            for (int nt = 0; nt < 4; nt++) {
                int col = wn * 32 + nt * 8 + gID;
                bb[nt][0] = fbits(Bs[kb + tig][col]);
                bb[nt][1] = fbits(Bs[kb + tig + 4][col]);
            }
            #pragma unroll
            for (int mt = 0; mt < 3; mt++)
                #pragma unroll
                for (int nt = 0; nt < 4; nt++)
                    mma_tf32(acc[mt][nt], a[mt], bb[nt]);
        }
        __syncthreads();
    }

    if (tid < 96) psum[tid] = 0.0f;
    __syncthreads();

    float* yb = g_y + (size_t)b * HID * HW;
    #pragma unroll
    for (int mt = 0; mt < 3; mt++) {
        #pragma unroll
        for (int h = 0; h < 2; h++) {
            int mr = wm * 48 + mt * 16 + gID + h * 8;   // row within block tile
            int m = m0 + mr;
            float sc = g1[m] * rsqrtf(v1[m] + EPS);
            float bi = bt1[m] - m1[m] * sc;
            float local = 0.0f;
            #pragma unroll
            for (int nt = 0; nt < 4; nt++) {
                int n = n0 + wn * 32 + nt * 8 + tig * 2;
                float v0 = fminf(fmaxf(acc[mt][nt][h * 2 + 0] * sc + bi, 0.0f), 6.0f);
                float v1c = fminf(fmaxf(acc[mt][nt][h * 2 + 1] * sc + bi, 0.0f), 6.0f);
                if (n < HW) {
                    *reinterpret_cast<float2*>(&yb[(size_t)m * HW + n]) = make_float2(v0, v1c);
                    local += v0 + v1c;
                }
            }
            atomicAdd(&psum[mr], local);
        }
    }
    __syncthreads();
    if (tid < 96) atomicAdd(&g_ypool[b * HID + m0 + tid], psum[tid]);
}

// ---------------- depthwise 3x3 + BN2 + ReLU6 (output tf32-rounded) ----------------
__global__ void k_dw(const float* __restrict__ g2, const float* __restrict__ bt2,
                     const float* __restrict__ m2, const float* __restrict__ v2) {
    int bc = blockIdx.x;                 // b*HID + ch
    int ch = bc % HID;
    __shared__ float t[58 * 58];
    const float* yin = g_y + (size_t)bc * HW;
    for (int i = threadIdx.x; i < 58 * 58; i += 256) {
        int r = i / 58, c = i % 58;
        int gr = r - 1, gc = c - 1;
        t[i] = (gr >= 0 && gr < WD && gc >= 0 && gc < WD) ? yin[gr * WD + gc] : 0.0f;
    }
    const float* kp = g_kw + bc * 9;
    float w0 = kp[0], w1 = kp[1], w2 = kp[2],
          w3 = kp[3], w4 = kp[4], w5 = kp[5],
          w6 = kp[6], w7 = kp[7], w8 = kp[8];
    float sc = g2[ch] * rsqrtf(v2[ch] + EPS);
    float bi = bt2[ch] - m2[ch] * sc;
    __syncthreads();
    float* yout = g_y2 + (size_t)bc * HW;
    for (int p = threadIdx.x; p < HW; p += 256) {
        int r = p / WD, c = p % WD;
        const float* tp = &t[r * 58 + c];
        float s = tp[0]   * w0 + tp[1]   * w1 + tp[2]   * w2
                + tp[58]  * w3 + tp[59]  * w4 + tp[60]  * w5
                + tp[116] * w6 + tp[117] * w7 + tp[118] * w8;
        s = s * sc + bi;
        s = fminf(fmaxf(s, 0.0f), 6.0f);
        yout[p] = to_tf32(s);
    }
}

// ---------------- project GEMM (tf32 tensor cores) ----------------
// out[b,m,n] = BN3( sum_k w3t[b,k,m] * y2[b,k,n] ) + x[b,m,n]
// block tile M=96 (full) x N=128, K=576 in chunks of 32.
__global__ __launch_bounds__(256, 2) void k_proj(const float* __restrict__ x,
        float* __restrict__ out,
        const float* __restrict__ g3, const float* __restrict__ bt3,
        const float* __restrict__ m3, const float* __restrict__ v3) {
    const int b = blockIdx.y, n0 = blockIdx.x * 128;
    __shared__ float As[32][104];
    __shared__ float Bs[32][136];
    const int tid = threadIdx.x, lane = tid & 31, wid = tid >> 5;
    const int wm = wid >> 2, wn = wid & 3;
    const int gID = lane >> 2, tig = lane & 3;
    float acc[3][4][4];
    #pragma unroll
    for (int i = 0; i < 3; i++)
        #pragma unroll
        for (int j = 0; j < 4; j++)
            #pragma unroll
            for (int q = 0; q < 4; q++) acc[i][j][q] = 0.0f;

    const float* Ag = g_w3t + (size_t)b * HID * COUT;  // [k][m=96]
    const float* Bg = g_y2  + (size_t)b * HID * HW;    // [k][n], already tf32

    for (int k0 = 0; k0 < HID; k0 += 32) {
        for (int i = tid; i < 32 * 96; i += 256) {
            int kk = i / 96, mm = i % 96;
            As[kk][mm] = Ag[(size_t)(k0 + kk) * COUT + mm];
        }
        for (int i = tid; i < 32 * 128; i += 256) {
            int kk = i >> 7, nn = i & 127;
            int n = n0 + nn;
            Bs[kk][nn] = (n < HW) ? Bg[(size_t)(k0 + kk) * HW + n] : 0.0f;
        }
        __syncthreads();
        #pragma unroll
        for (int ks = 0; ks < 4; ks++) {
            const int kb = ks * 8;
            uint32_t a[3][4], bb[4][2];
            #pragma unroll
            for (int mt = 0; mt < 3; mt++) {
                int row = wm * 48 + mt * 16 + gID;
                a[mt][0] = fbits(As[kb + tig][row]);
                a[mt][1] = fbits(As[kb + tig][row + 8]);
                a[mt][2] = fbits(As[kb + tig + 4][row]);
                a[mt][3] = fbits(As[kb + tig + 4][row + 8]);
            }
            #pragma unroll
            for (int nt = 0; nt < 4; nt++) {
                int col = wn * 32 + nt * 8 + gID;
                bb[nt][0] = fbits(Bs[kb + tig][col]);
                bb[nt][1] = fbits(Bs[kb + tig + 4][col]);
            }
            #pragma unroll
            for (int mt = 0; mt < 3; mt++)
                #pragma unroll
                for (int nt = 0; nt < 4; nt++)
                    mma_tf32(acc[mt][nt], a[mt], bb[nt]);
        }
        __syncthreads();
    }

    const float* xb = x + (size_t)b * CIN * HW;
    float* ob = out + (size_t)b * COUT * HW;
    #pragma unroll
    for (int mt = 0; mt < 3; mt++) {
        #pragma unroll
        for (int h = 0; h < 2; h++) {
            int m = wm * 48 + mt * 16 + gID + h * 8;
            float sc = g3[m] * rsqrtf(v3[m] + EPS);
            float bi = bt3[m] - m3[m] * sc;
            #pragma unroll
            for (int nt = 0; nt < 4; nt++) {
                int n = n0 + wn * 32 + nt * 8 + tig * 2;
                if (n < HW) {
                    float2 xv = *reinterpret_cast<const float2*>(&xb[(size_t)m * HW + n]);
                    float v0 = acc[mt][nt][h * 2 + 0] * sc + bi + xv.x;
                    float v1c = acc[mt][nt][h * 2 + 1] * sc + bi + xv.y;
                    *reinterpret_cast<float2*>(&ob[(size_t)m * HW + n]) = make_float2(v0, v1c);
                }
            }
        }
    }
}

// ---------------- launcher ----------------
extern "C" void kernel_launch(void* const* d_in, const int* in_sizes, int n_in,
                              void* d_out, int out_size) {
    const float* x    = (const float*)d_in[0];
    const float* w_r1 = (const float*)d_in[1];
    const float* b_r1 = (const float*)d_in[2];
    const float* w1   = (const float*)d_in[3];
    const float* g1   = (const float*)d_in[4];
    const float* bt1  = (const float*)d_in[5];
    const float* m1   = (const float*)d_in[6];
    const float* v1   = (const float*)d_in[7];
    const float* w_r2 = (const float*)d_in[8];
    const float* b_r2 = (const float*)d_in[9];
    const float* w2   = (const float*)d_in[10];
    const float* g2   = (const float*)d_in[11];
    const float* bt2  = (const float*)d_in[12];
    const float* m2   = (const float*)d_in[13];
    const float* v2   = (const float*)d_in[14];
    const float* w3   = (const float*)d_in[15];
    const float* g3   = (const float*)d_in[16];
    const float* bt3  = (const float*)d_in[17];
    const float* m3   = (const float*)d_in[18];
    const float* v3   = (const float*)d_in[19];
    const float* w_r3 = (const float*)d_in[20];
    const float* b_r3 = (const float*)d_in[21];
    float* out = (float*)d_out;

    k_zero_ypool<<<(B_ * HID + 255) / 256, 256>>>();
    k_xpool<<<B_ * CIN, 256>>>(x);
    k_route1<<<1, 256>>>(w_r1, b_r1, w_r3, b_r3);
    k_mix1<<<dim3(CIN / 32, HID / 32, B_), 256>>>(w1);   // (3, 18, 32)
    k_mix3<<<dim3(HID / 32, COUT / 32, B_), 256>>>(w3);  // (18, 3, 32)
    k_expand<<<dim3(25, 6, B_), 256>>>(x, g1, bt1, m1, v1);
    k_route2<<<B_, 256>>>(w_r2, b_r2, w2);
    k_dw<<<B_ * HID, 256>>>(g2, bt2, m2, v2);
    k_proj<<<dim3(25, B_), 256>>>(x, out, g3, bt3, m3, v3);
}

// round 3
// speedup vs baseline: 2.5990x; 1.6280x over previous
#include <cuda_runtime.h>
#include <cuda_fp16.h>
#include <math.h>
#include <stdint.h>

#define B_    32
#define CIN   96
#define COUT  96
#define HID   576
#define E_    8
#define HW    3136
#define WD    56
#define EPS   1e-5f

// ---------------- scratch (device globals; no allocation) ----------------
__device__ __half g_yh  [(size_t)B_*HID*HW];  // expanded activations (post BN1+ReLU6), fp16
__device__ __half g_y2h [(size_t)B_*HID*HW];  // after depthwise (post BN2+ReLU6), fp16
__device__ float  g_xpool[B_*CIN];
__device__ float  g_ypool[B_*HID];            // sum of y over HW (fp32)
__device__ float  g_r1  [B_*E_];
__device__ float  g_rblk[B_*E_];
__device__ __half g_w1h [(size_t)B_*HID*CIN]; // mixed expand weights [b][m=HID][k=CIN], fp16
__device__ __half g_w3h [(size_t)B_*COUT*HID];// mixed project weights [b][m=COUT][k=HID], fp16
__device__ float  g_kw  [B_*HID*9];           // mixed depthwise kernels (fp32)

// ---------------- helpers ----------------
__device__ __forceinline__ void mma_f16(float d[4], const uint32_t a[4], const uint32_t b[2]) {
    asm volatile(
        "mma.sync.aligned.m16n8k16.row.col.f32.f16.f16.f32 "
        "{%0,%1,%2,%3}, {%4,%5,%6,%7}, {%8,%9}, {%0,%1,%2,%3};"
        : "+f"(d[0]), "+f"(d[1]), "+f"(d[2]), "+f"(d[3])
        : "r"(a[0]), "r"(a[1]), "r"(a[2]), "r"(a[3]), "r"(b[0]), "r"(b[1]));
}
__device__ __forceinline__ uint32_t h2bits(__half2 h) { return *reinterpret_cast<uint32_t*>(&h); }

#define ASTRIDE 40   // halves per row; 20 words -> conflict-free fragment LDS

// ---------------- small kernels ----------------
__global__ void k_zero_ypool() {
    int i = blockIdx.x * 256 + threadIdx.x;
    if (i < B_ * HID) g_ypool[i] = 0.0f;
}

__global__ void k_xpool(const float* __restrict__ x) {
    int bc = blockIdx.x;
    const float* p = x + (size_t)bc * HW;
    float s = 0.0f;
    for (int i = threadIdx.x; i < HW; i += 256) s += p[i];
    __shared__ float sm[256];
    sm[threadIdx.x] = s; __syncthreads();
    for (int o = 128; o > 0; o >>= 1) {
        if (threadIdx.x < o) sm[threadIdx.x] += sm[threadIdx.x + o];
        __syncthreads();
    }
    if (threadIdx.x == 0) g_xpool[bc] = sm[0] * (1.0f / HW);
}

__global__ void k_route1(const float* __restrict__ wr1, const float* __restrict__ br1,
                         const float* __restrict__ wr3, const float* __restrict__ br3) {
    int t = threadIdx.x;          // 256 threads = 32 b * 8 e
    int b = t >> 3, e = t & 7;
    const float* xp = g_xpool + b * CIN;
    float s1 = br1[e], s3 = br3[e];
    #pragma unroll 4
    for (int c = 0; c < CIN; c++) {
        float xv = xp[c];
        s1 += xv * wr1[e * CIN + c];
        s3 += xv * wr3[e * CIN + c];
    }
    g_r1[t]   = 1.0f / (1.0f + expf(-s1));
    g_rblk[t] = 1.0f / (1.0f + expf(-s3));
}

// mix (fp32 accumulate) -> fp16 weights, natural [m][k] layout
__global__ void k_mix1(const float* __restrict__ w1) {
    int b = blockIdx.y;
    int i = blockIdx.x * 256 + threadIdx.x;
    if (i >= HID * CIN) return;
    const float* r = g_r1 + b * E_;
    float s = 0.0f;
    #pragma unroll
    for (int e = 0; e < E_; e++) s += r[e] * w1[(size_t)e * HID * CIN + i];
    g_w1h[(size_t)b * HID * CIN + i] = __float2half_rn(s);
}

__global__ void k_mix3(const float* __restrict__ w3) {
    int b = blockIdx.y;
    int i = blockIdx.x * 256 + threadIdx.x;
    if (i >= COUT * HID) return;
    const float* r = g_rblk + b * E_;
    float s = 0.0f;
    #pragma unroll
    for (int e = 0; e < E_; e++) s += r[e] * w3[(size_t)e * COUT * HID + i];
    g_w3h[(size_t)b * COUT * HID + i] = __float2half_rn(s);
}

__global__ void k_route2(const float* __restrict__ wr2, const float* __restrict__ br2,
                         const float* __restrict__ w2) {
    int b = blockIdx.x;
    __shared__ float rs[E_];
    if (threadIdx.x < E_) {
        int e = threadIdx.x;
        float s = br2[e];
        const float* yp = g_ypool + b * HID;
        #pragma unroll 4
        for (int c = 0; c < HID; c++)
            s += (yp[c] * (1.0f / HW)) * wr2[e * HID + c];
        rs[e] = 1.0f / (1.0f + expf(-s));
    }
    __syncthreads();
    for (int i = threadIdx.x; i < HID * 9; i += 256) {
        float s = 0.0f;
        #pragma unroll
        for (int e = 0; e < E_; e++) s += rs[e] * w2[(size_t)e * HID * 9 + i];
        g_kw[b * HID * 9 + i] = s;
    }
}

// ---------------- expand GEMM (fp16 mma, fp32 accum) ----------------
// y[b,m,n] = BN1/ReLU6( sum_k w1h[b,m,k] * x[b,k,n] ),  fused ypool reduction.
// block tile M=96 x N=128, K-chunk 32; 8 warps as 2(m) x 4(n); warp tile 48x32.
__global__ __launch_bounds__(256) void k_expand(const float* __restrict__ x,
        const float* __restrict__ g1, const float* __restrict__ bt1,
        const float* __restrict__ m1, const float* __restrict__ v1) {
    const int b = blockIdx.z, m0 = blockIdx.y * 96, n0 = blockIdx.x * 128;
    __shared__ __align__(16) __half As[96 * ASTRIDE];   // [m][k]
    __shared__ __align__(16) __half Bs[128 * ASTRIDE];  // [n][k]
    __shared__ float psum[96];
    const int tid = threadIdx.x, lane = tid & 31, wid = tid >> 5;
    const int wm = wid >> 2, wn = wid & 3;
    const int gID = lane >> 2, tig = lane & 3;
    float acc[3][4][4];
    #pragma unroll
    for (int i = 0; i < 3; i++)
        #pragma unroll
        for (int j = 0; j < 4; j++)
            #pragma unroll
            for (int q = 0; q < 4; q++) acc[i][j][q] = 0.0f;

    const __half* Ag = g_w1h + (size_t)b * HID * CIN;   // [m][k]
    const float*  Bg = x     + (size_t)b * CIN * HW;    // [k][n]

    for (int k0 = 0; k0 < CIN; k0 += 32) {
        // stage A: 96 x 32 halves (half2 copies)
        #pragma unroll
        for (int i = tid; i < 1536; i += 256) {
            int row = i >> 4, cp = i & 15;
            *reinterpret_cast<__half2*>(&As[row * ASTRIDE + 2 * cp]) =
                *reinterpret_cast<const __half2*>(&Ag[(size_t)(m0 + row) * CIN + k0 + 2 * cp]);
        }
        // stage B transposed: read float2 along n from rows k,k+1; write half2 along k
        #pragma unroll
        for (int i = tid; i < 1024; i += 256) {
            int n2 = (i & 63) * 2, kp = i >> 6;
            int n = n0 + n2;
            float2 va = make_float2(0.f, 0.f), vb = make_float2(0.f, 0.f);
            if (n < HW) {
                va = *reinterpret_cast<const float2*>(&Bg[(size_t)(k0 + 2 * kp) * HW + n]);
                vb = *reinterpret_cast<const float2*>(&Bg[(size_t)(k0 + 2 * kp + 1) * HW + n]);
            }
            *reinterpret_cast<__half2*>(&Bs[n2 * ASTRIDE + 2 * kp]) = __floats2half2_rn(va.x, vb.x);
            *reinterpret_cast<__half2*>(&Bs[(n2 + 1) * ASTRIDE + 2 * kp]) = __floats2half2_rn(va.y, vb.y);
        }
        __syncthreads();
        #pragma unroll
        for (int ks = 0; ks < 2; ks++) {
            const int kb = ks * 16;
            uint32_t a[3][4], bb[4][2];
            #pragma unroll
            for (int mt = 0; mt < 3; mt++) {
                int row = wm * 48 + mt * 16 + gID;
                const __half* p0 = &As[row * ASTRIDE + kb + 2 * tig];
                const __half* p1 = &As[(row + 8) * ASTRIDE + kb + 2 * tig];
                a[mt][0] = h2bits(*reinterpret_cast<const __half2*>(p0));
                a[mt][1] = h2bits(*reinterpret_cast<const __half2*>(p1));
                a[mt][2] = h2bits(*reinterpret_cast<const __half2*>(p0 + 8));
                a[mt][3] = h2bits(*reinterpret_cast<const __half2*>(p1 + 8));
            }
            #pragma unroll
            for (int nt = 0; nt < 4; nt++) {
                int col = wn * 32 + nt * 8 + gID;
                const __half* p = &Bs[col * ASTRIDE + kb + 2 * tig];
                bb[nt][0] = h2bits(*reinterpret_cast<const __half2*>(p));
                bb[nt][1] = h2bits(*reinterpret_cast<const __half2*>(p + 8));
            }
            #pragma unroll
            for (int mt = 0; mt < 3; mt++)
                #pragma unroll
                for (int nt = 0; nt < 4; nt++)
                    mma_f16(acc[mt][nt], a[mt], bb[nt]);
        }
        __syncthreads();
    }

    if (tid < 96) psum[tid] = 0.0f;
    __syncthreads();

    __half* yb = g_yh + (size_t)b * HID * HW;
    #pragma unroll
    for (int mt = 0; mt < 3; mt++) {
        #pragma unroll
        for (int h = 0; h < 2; h++) {
            int mr = wm * 48 + mt * 16 + gID + h * 8;
            int m = m0 + mr;
            float sc = g1[m] * rsqrtf(v1[m] + EPS);
            float bi = bt1[m] - m1[m] * sc;
            float local = 0.0f;
            #pragma unroll
            for (int nt = 0; nt < 4; nt++) {
                int n = n0 + wn * 32 + nt * 8 + tig * 2;
                float v0 = fminf(fmaxf(acc[mt][nt][h * 2 + 0] * sc + bi, 0.0f), 6.0f);
                float v1c = fminf(fmaxf(acc[mt][nt][h * 2 + 1] * sc + bi, 0.0f), 6.0f);
                if (n < HW) {
                    *reinterpret_cast<__half2*>(&yb[(size_t)m * HW + n]) = __floats2half2_rn(v0, v1c);
                    local += v0 + v1c;
                }
            }
            atomicAdd(&psum[mr], local);
        }
    }
    __syncthreads();
    if (tid < 96) atomicAdd(&g_ypool[b * HID + m0 + tid], psum[tid]);
}

// ---------------- depthwise 3x3 + BN2 + ReLU6 (fp16 in/out, fp32 math) ----------------
__global__ void k_dw(const float* __restrict__ g2, const float* __restrict__ bt2,
                     const float* __restrict__ m2, const float* __restrict__ v2) {
    int bc = blockIdx.x;                 // b*HID + ch
    int ch = bc % HID;
    __shared__ float t[58 * 58];
    const __half* yin = g_yh + (size_t)bc * HW;
    for (int i = threadIdx.x; i < 58 * 58; i += 256) {
        int r = i / 58, c = i % 58;
        int gr = r - 1, gc = c - 1;
        t[i] = (gr >= 0 && gr < WD && gc >= 0 && gc < WD) ? __half2float(yin[gr * WD + gc]) : 0.0f;
    }
    const float* kp = g_kw + bc * 9;
    float w0 = kp[0], w1 = kp[1], w2 = kp[2],
          w3 = kp[3], w4 = kp[4], w5 = kp[5],
          w6 = kp[6], w7 = kp[7], w8 = kp[8];
    float sc = g2[ch] * rsqrtf(v2[ch] + EPS);
    float bi = bt2[ch] - m2[ch] * sc;
    __syncthreads();
    __half* yout = g_y2h + (size_t)bc * HW;
    for (int p = threadIdx.x; p < HW; p += 256) {
        int r = p / WD, c = p % WD;
        const float* tp = &t[r * 58 + c];
        float s = tp[0]   * w0 + tp[1]   * w1 + tp[2]   * w2
                + tp[58]  * w3 + tp[59]  * w4 + tp[60]  * w5
                + tp[116] * w6 + tp[117] * w7 + tp[118] * w8;
        s = s * sc + bi;
        s = fminf(fmaxf(s, 0.0f), 6.0f);
        yout[p] = __float2half_rn(s);
    }
}

// ---------------- project GEMM (fp16 mma, fp32 accum) ----------------
// out[b,m,n] = BN3( sum_k w3h[b,m,k] * y2h[b,k,n] ) + x[b,m,n]
__global__ __launch_bounds__(256) void k_proj(const float* __restrict__ x,
        float* __restrict__ out,
        const float* __restrict__ g3, const float* __restrict__ bt3,
        const float* __restrict__ m3, const float* __restrict__ v3) {
    const int b = blockIdx.y, n0 = blockIdx.x * 128;
    __shared__ __align__(16) __half As[96 * ASTRIDE];   // [m][k]
    __shared__ __align__(16) __half Bs[128 * ASTRIDE];  // [n][k]
    const int tid = threadIdx.x, lane = tid & 31, wid = tid >> 5;
    const int wm = wid >> 2, wn = wid & 3;
    const int gID = lane >> 2, tig = lane & 3;
    float acc[3][4][4];
    #pragma unroll
    for (int i = 0; i < 3; i++)
        #pragma unroll
        for (int j = 0; j < 4; j++)
            #pragma unroll
            for (int q = 0; q < 4; q++) acc[i][j][q] = 0.0f;

    const __half* Ag = g_w3h + (size_t)b * COUT * HID;  // [m=96][k]
    const __half* Bg = g_y2h + (size_t)b * HID * HW;    // [k][n]

    for (int k0 = 0; k0 < HID; k0 += 32) {
        #pragma unroll
        for (int i = tid; i < 1536; i += 256) {
            int row = i >> 4, cp = i & 15;
            *reinterpret_cast<__half2*>(&As[row * ASTRIDE + 2 * cp]) =
                *reinterpret_cast<const __half2*>(&Ag[(size_t)row * HID + k0 + 2 * cp]);
        }
        #pragma unroll
        for (int i = tid; i < 1024; i += 256) {
            int n2 = (i & 63) * 2, kp = i >> 6;
            int n = n0 + n2;
            __half2 va = __floats2half2_rn(0.f, 0.f), vb = va;
            if (n < HW) {
                va = *reinterpret_cast<const __half2*>(&Bg[(size_t)(k0 + 2 * kp) * HW + n]);
                vb = *reinterpret_cast<const __half2*>(&Bg[(size_t)(k0 + 2 * kp + 1) * HW + n]);
            }
            *reinterpret_cast<__half2*>(&Bs[n2 * ASTRIDE + 2 * kp]) = __halves2half2(__low2half(va), __low2half(vb));
            *reinterpret_cast<__half2*>(&Bs[(n2 + 1) * ASTRIDE + 2 * kp]) = __halves2half2(__high2half(va), __high2half(vb));
        }
        __syncthreads();
        #pragma unroll
        for (int ks = 0; ks < 2; ks++) {
            const int kb = ks * 16;
            uint32_t a[3][4], bb[4][2];
            #pragma unroll
            for (int mt = 0; mt < 3; mt++) {
                int row = wm * 48 + mt * 16 + gID;
                const __half* p0 = &As[row * ASTRIDE + kb + 2 * tig];
                const __half* p1 = &As[(row + 8) * ASTRIDE + kb + 2 * tig];
                a[mt][0] = h2bits(*reinterpret_cast<const __half2*>(p0));
                a[mt][1] = h2bits(*reinterpret_cast<const __half2*>(p1));
                a[mt][2] = h2bits(*reinterpret_cast<const __half2*>(p0 + 8));
                a[mt][3] = h2bits(*reinterpret_cast<const __half2*>(p1 + 8));
            }
            #pragma unroll
            for (int nt = 0; nt < 4; nt++) {
                int col = wn * 32 + nt * 8 + gID;
                const __half* p = &Bs[col * ASTRIDE + kb + 2 * tig];
                bb[nt][0] = h2bits(*reinterpret_cast<const __half2*>(p));
                bb[nt][1] = h2bits(*reinterpret_cast<const __half2*>(p + 8));
            }
            #pragma unroll
            for (int mt = 0; mt < 3; mt++)
                #pragma unroll
                for (int nt = 0; nt < 4; nt++)
                    mma_f16(acc[mt][nt], a[mt], bb[nt]);
        }
        __syncthreads();
    }

    const float* xb = x + (size_t)b * CIN * HW;
    float* ob = out + (size_t)b * COUT * HW;
    #pragma unroll
    for (int mt = 0; mt < 3; mt++) {
        #pragma unroll
        for (int h = 0; h < 2; h++) {
            int m = wm * 48 + mt * 16 + gID + h * 8;
            float sc = g3[m] * rsqrtf(v3[m] + EPS);
            float bi = bt3[m] - m3[m] * sc;
            #pragma unroll
            for (int nt = 0; nt < 4; nt++) {
                int n = n0 + wn * 32 + nt * 8 + tig * 2;
                if (n < HW) {
                    float2 xv = *reinterpret_cast<const float2*>(&xb[(size_t)m * HW + n]);
                    float v0 = acc[mt][nt][h * 2 + 0] * sc + bi + xv.x;
                    float v1c = acc[mt][nt][h * 2 + 1] * sc + bi + xv.y;
                    *reinterpret_cast<float2*>(&ob[(size_t)m * HW + n]) = make_float2(v0, v1c);
                }
            }
        }
    }
}

// ---------------- launcher ----------------
extern "C" void kernel_launch(void* const* d_in, const int* in_sizes, int n_in,
                              void* d_out, int out_size) {
    const float* x    = (const float*)d_in[0];
    const float* w_r1 = (const float*)d_in[1];
    const float* b_r1 = (const float*)d_in[2];
    const float* w1   = (const float*)d_in[3];
    const float* g1   = (const float*)d_in[4];
    const float* bt1  = (const float*)d_in[5];
    const float* m1   = (const float*)d_in[6];
    const float* v1   = (const float*)d_in[7];
    const float* w_r2 = (const float*)d_in[8];
    const float* b_r2 = (const float*)d_in[9];
    const float* w2   = (const float*)d_in[10];
    const float* g2   = (const float*)d_in[11];
    const float* bt2  = (const float*)d_in[12];
    const float* m2   = (const float*)d_in[13];
    const float* v2   = (const float*)d_in[14];
    const float* w3   = (const float*)d_in[15];
    const float* g3   = (const float*)d_in[16];
    const float* bt3  = (const float*)d_in[17];
    const float* m3   = (const float*)d_in[18];
    const float* v3   = (const float*)d_in[19];
    const float* w_r3 = (const float*)d_in[20];
    const float* b_r3 = (const float*)d_in[21];
    float* out = (float*)d_out;

    k_zero_ypool<<<(B_ * HID + 255) / 256, 256>>>();
    k_xpool<<<B_ * CIN, 256>>>(x);
    k_route1<<<1, 256>>>(w_r1, b_r1, w_r3, b_r3);
    k_mix1<<<dim3(216, B_), 256>>>(w1);
    k_mix3<<<dim3(216, B_), 256>>>(w3);
    k_expand<<<dim3(25, 6, B_), 256>>>(x, g1, bt1, m1, v1);
    k_route2<<<B_, 256>>>(w_r2, b_r2, w2);
    k_dw<<<B_ * HID, 256>>>(g2, bt2, m2, v2);
    k_proj<<<dim3(25, B_), 256>>>(x, out, g3, bt3, m3, v3);
}

// round 4
// speedup vs baseline: 3.4287x; 1.3193x over previous
#include <cuda_runtime.h>
#include <cuda_fp16.h>
#include <math.h>
#include <stdint.h>

#define B_    32
#define CIN   96
#define COUT  96
#define HID   576
#define E_    8
#define HW    3136
#define WD    56
#define EPS   1e-5f

// ---------------- scratch (device globals; no allocation) ----------------
__device__ __half g_xh  [(size_t)B_*CIN*HW];  // x converted to fp16
__device__ __half g_yh  [(size_t)B_*HID*HW];  // expanded activations (post BN1+ReLU6), fp16
__device__ __half g_y2h [(size_t)B_*HID*HW];  // after depthwise (post BN2+ReLU6), fp16
__device__ float  g_xpool[B_*CIN];
__device__ float  g_ypool[B_*HID];            // sum of y over HW (fp32)
__device__ float  g_r1  [B_*E_];
__device__ float  g_rblk[B_*E_];
__device__ __half g_w1h [(size_t)B_*HID*CIN]; // mixed expand weights [b][m=HID][k=CIN], fp16
__device__ __half g_w3h [(size_t)B_*COUT*HID];// mixed project weights [b][m=COUT][k=HID], fp16
__device__ float  g_kw  [B_*HID*9];           // mixed depthwise kernels (fp32)

// ---------------- helpers ----------------
__device__ __forceinline__ void mma_f16(float d[4], const uint32_t a[4], const uint32_t b[2]) {
    asm volatile(
        "mma.sync.aligned.m16n8k16.row.col.f32.f16.f16.f32 "
        "{%0,%1,%2,%3}, {%4,%5,%6,%7}, {%8,%9}, {%0,%1,%2,%3};"
        : "+f"(d[0]), "+f"(d[1]), "+f"(d[2]), "+f"(d[3])
        : "r"(a[0]), "r"(a[1]), "r"(a[2]), "r"(a[3]), "r"(b[0]), "r"(b[1]));
}
__device__ __forceinline__ uint32_t h2bits(__half2 h) { return *reinterpret_cast<uint32_t*>(&h); }

#define ASTRIDE 40   // halves per row; 20 words -> conflict-free fragment LDS

// ---------------- xpool + fp16 conversion of x (single pass over x) ----------------
__global__ void k_xpool(const float* __restrict__ x) {
    int bc = blockIdx.x;
    const float4* p = reinterpret_cast<const float4*>(x + (size_t)bc * HW);
    __half2* xo = reinterpret_cast<__half2*>(g_xh + (size_t)bc * HW);
    float s = 0.0f;
    for (int i = threadIdx.x; i < HW / 4; i += 256) {
        float4 v = p[i];
        s += (v.x + v.y) + (v.z + v.w);
        xo[2 * i]     = __floats2half2_rn(v.x, v.y);
        xo[2 * i + 1] = __floats2half2_rn(v.z, v.w);
    }
    // warp then block reduce
    #pragma unroll
    for (int o = 16; o > 0; o >>= 1) s += __shfl_xor_sync(0xffffffffu, s, o);
    __shared__ float sm[8];
    if ((threadIdx.x & 31) == 0) sm[threadIdx.x >> 5] = s;
    __syncthreads();
    if (threadIdx.x == 0) {
        float t = 0.0f;
        #pragma unroll
        for (int w = 0; w < 8; w++) t += sm[w];
        g_xpool[bc] = t * (1.0f / HW);
    }
}

// ---------------- routers for expand + block (also zeros ypool) ----------------
__global__ void k_route1(const float* __restrict__ wr1, const float* __restrict__ br1,
                         const float* __restrict__ wr3, const float* __restrict__ br3) {
    for (int i = threadIdx.x; i < B_ * HID; i += 256) g_ypool[i] = 0.0f;
    int t = threadIdx.x;          // 256 threads = 32 b * 8 e
    int b = t >> 3, e = t & 7;
    const float* xp = g_xpool + b * CIN;
    float s1 = br1[e], s3 = br3[e];
    #pragma unroll 4
    for (int c = 0; c < CIN; c++) {
        float xv = xp[c];
        s1 += xv * wr1[e * CIN + c];
        s3 += xv * wr3[e * CIN + c];
    }
    g_r1[t]   = 1.0f / (1.0f + expf(-s1));
    g_rblk[t] = 1.0f / (1.0f + expf(-s3));
}

// ---------------- merged mix (fp32 accumulate) -> fp16 weights, [m][k] ----------------
__global__ void k_mix(const float* __restrict__ w1, const float* __restrict__ w3) {
    int bw = blockIdx.y;
    int b = bw & 31;
    int i = blockIdx.x * 256 + threadIdx.x;
    if (i >= HID * CIN) return;
    if (bw < B_) {
        const float* r = g_r1 + b * E_;
        float s = 0.0f;
        #pragma unroll
        for (int e = 0; e < E_; e++) s += r[e] * w1[(size_t)e * HID * CIN + i];
        g_w1h[(size_t)b * HID * CIN + i] = __float2half_rn(s);
    } else {
        const float* r = g_rblk + b * E_;
        float s = 0.0f;
        #pragma unroll
        for (int e = 0; e < E_; e++) s += r[e] * w3[(size_t)e * COUT * HID + i];
        g_w3h[(size_t)b * COUT * HID + i] = __float2half_rn(s);
    }
}

// ---------------- router2 + depthwise kernel mixing ----------------
__global__ void k_route2(const float* __restrict__ wr2, const float* __restrict__ br2,
                         const float* __restrict__ w2) {
    int b = blockIdx.x;
    __shared__ float rs[E_];
    int w = threadIdx.x >> 5, lane = threadIdx.x & 31;   // 8 warps = 8 experts
    {
        const float* yp = g_ypool + b * HID;
        float s = 0.0f;
        for (int c = lane; c < HID; c += 32) s += yp[c] * wr2[w * HID + c];
        #pragma unroll
        for (int o = 16; o > 0; o >>= 1) s += __shfl_xor_sync(0xffffffffu, s, o);
        if (lane == 0) rs[w] = 1.0f / (1.0f + expf(-(s * (1.0f / HW) + br2[w])));
    }
    __syncthreads();
    for (int i = threadIdx.x; i < HID * 9; i += 256) {
        float s = 0.0f;
        #pragma unroll
        for (int e = 0; e < E_; e++) s += rs[e] * w2[(size_t)e * HID * 9 + i];
        g_kw[b * HID * 9 + i] = s;
    }
}

// ---------------- expand GEMM (fp16 mma, fp32 accum, sw pipelined) ----------------
// y[b,m,n] = BN1/ReLU6( sum_k w1h[b,m,k] * xh[b,k,n] ),  fused ypool reduction.
__global__ __launch_bounds__(256) void k_expand(
        const float* __restrict__ g1, const float* __restrict__ bt1,
        const float* __restrict__ m1, const float* __restrict__ v1) {
    const int b = blockIdx.z, m0 = blockIdx.y * 96, n0 = blockIdx.x * 128;
    __shared__ __align__(16) __half As[96 * ASTRIDE];   // [m][k]
    __shared__ __align__(16) __half Bs[128 * ASTRIDE];  // [n][k]
    __shared__ float psum[96];
    const int tid = threadIdx.x, lane = tid & 31, wid = tid >> 5;
    const int wm = wid >> 2, wn = wid & 3;
    const int gID = lane >> 2, tig = lane & 3;
    float acc[3][4][4];
    #pragma unroll
    for (int i = 0; i < 3; i++)
        #pragma unroll
        for (int j = 0; j < 4; j++)
            #pragma unroll
            for (int q = 0; q < 4; q++) acc[i][j][q] = 0.0f;

    const __half* Ag = g_w1h + (size_t)b * HID * CIN;   // [m][k]
    const __half* Bg = g_xh  + (size_t)b * CIN * HW;    // [k][n] fp16

    __half2 pa[6], pb[4][2];
    const __half2 hz = __floats2half2_rn(0.f, 0.f);

    auto load_chunk = [&](int k0) {
        #pragma unroll
        for (int j = 0; j < 6; j++) {
            int i = tid + j * 256;
            int row = i >> 4, cp = i & 15;
            pa[j] = *reinterpret_cast<const __half2*>(&Ag[(size_t)(m0 + row) * CIN + k0 + 2 * cp]);
        }
        #pragma unroll
        for (int j = 0; j < 4; j++) {
            int i = tid + j * 256;
            int n2 = (i & 63) * 2, kp = i >> 6;
            int n = n0 + n2;
            if (n < HW) {
                pb[j][0] = *reinterpret_cast<const __half2*>(&Bg[(size_t)(k0 + 2 * kp) * HW + n]);
                pb[j][1] = *reinterpret_cast<const __half2*>(&Bg[(size_t)(k0 + 2 * kp + 1) * HW + n]);
            } else { pb[j][0] = hz; pb[j][1] = hz; }
        }
    };
    auto store_chunk = [&]() {
        #pragma unroll
        for (int j = 0; j < 6; j++) {
            int i = tid + j * 256;
            int row = i >> 4, cp = i & 15;
            *reinterpret_cast<__half2*>(&As[row * ASTRIDE + 2 * cp]) = pa[j];
        }
        #pragma unroll
        for (int j = 0; j < 4; j++) {
            int i = tid + j * 256;
            int n2 = (i & 63) * 2, kp = i >> 6;
            *reinterpret_cast<__half2*>(&Bs[n2 * ASTRIDE + 2 * kp]) =
                __halves2half2(__low2half(pb[j][0]), __low2half(pb[j][1]));
            *reinterpret_cast<__half2*>(&Bs[(n2 + 1) * ASTRIDE + 2 * kp]) =
                __halves2half2(__high2half(pb[j][0]), __high2half(pb[j][1]));
        }
    };

    load_chunk(0);
    #pragma unroll
    for (int c = 0; c < 3; c++) {
        store_chunk();
        __syncthreads();
        if (c < 2) load_chunk((c + 1) * 32);
        #pragma unroll
        for (int ks = 0; ks < 2; ks++) {
            const int kb = ks * 16;
            uint32_t a[3][4], bb[4][2];
            #pragma unroll
            for (int mt = 0; mt < 3; mt++) {
                int row = wm * 48 + mt * 16 + gID;
                const __half* p0 = &As[row * ASTRIDE + kb + 2 * tig];
                const __half* p1 = &As[(row + 8) * ASTRIDE + kb + 2 * tig];
                a[mt][0] = h2bits(*reinterpret_cast<const __half2*>(p0));
                a[mt][1] = h2bits(*reinterpret_cast<const __half2*>(p1));
                a[mt][2] = h2bits(*reinterpret_cast<const __half2*>(p0 + 8));
                a[mt][3] = h2bits(*reinterpret_cast<const __half2*>(p1 + 8));
            }
            #pragma unroll
            for (int nt = 0; nt < 4; nt++) {
                int col = wn * 32 + nt * 8 + gID;
                const __half* p = &Bs[col * ASTRIDE + kb + 2 * tig];
                bb[nt][0] = h2bits(*reinterpret_cast<const __half2*>(p));
                bb[nt][1] = h2bits(*reinterpret_cast<const __half2*>(p + 8));
            }
            #pragma unroll
            for (int mt = 0; mt < 3; mt++)
                #pragma unroll
                for (int nt = 0; nt < 4; nt++)
                    mma_f16(acc[mt][nt], a[mt], bb[nt]);
        }
        __syncthreads();
    }

    if (tid < 96) psum[tid] = 0.0f;
    __syncthreads();

    __half* yb = g_yh + (size_t)b * HID * HW;
    #pragma unroll
    for (int mt = 0; mt < 3; mt++) {
        #pragma unroll
        for (int h = 0; h < 2; h++) {
            int mr = wm * 48 + mt * 16 + gID + h * 8;
            int m = m0 + mr;
            float sc = g1[m] * rsqrtf(v1[m] + EPS);
            float bi = bt1[m] - m1[m] * sc;
            float local = 0.0f;
            #pragma unroll
            for (int nt = 0; nt < 4; nt++) {
                int n = n0 + wn * 32 + nt * 8 + tig * 2;
                float v0 = fminf(fmaxf(acc[mt][nt][h * 2 + 0] * sc + bi, 0.0f), 6.0f);
                float v1c = fminf(fmaxf(acc[mt][nt][h * 2 + 1] * sc + bi, 0.0f), 6.0f);
                if (n < HW) {
                    *reinterpret_cast<__half2*>(&yb[(size_t)m * HW + n]) = __floats2half2_rn(v0, v1c);
                    local += v0 + v1c;
                }
            }
            atomicAdd(&psum[mr], local);
        }
    }
    __syncthreads();
    if (tid < 96) atomicAdd(&g_ypool[b * HID + m0 + tid], psum[tid]);
}

// ---------------- depthwise 3x3 + BN2 + ReLU6 (vectorized) ----------------
#define TS 60   // smem row stride (floats)
__global__ void k_dw(const float* __restrict__ g2, const float* __restrict__ bt2,
                     const float* __restrict__ m2, const float* __restrict__ v2) {
    int bc = blockIdx.x;                 // b*HID + ch
    int ch = bc % HID;
    __shared__ float t[58 * TS];
    const __half2* yin2 = reinterpret_cast<const __half2*>(g_yh + (size_t)bc * HW);
    // interior: rows 1..56, cols 1..56
    for (int i = threadIdx.x; i < HW / 2; i += 256) {
        int r = i / 28, c = (i - r * 28) * 2;
        float2 v = __half22float2(yin2[i]);
        float* dst = &t[(r + 1) * TS + c + 1];
        dst[0] = v.x; dst[1] = v.y;
    }
    // halo zero: 228 cells
    for (int i = threadIdx.x; i < 228; i += 256) {
        int idx;
        if (i < 58)       idx = i;                       // row 0
        else if (i < 116) idx = 57 * TS + (i - 58);      // row 57
        else if (i < 172) idx = (i - 115) * TS;          // col 0, rows 1..56
        else              idx = (i - 171) * TS + 57;     // col 57, rows 1..56
        t[idx] = 0.0f;
    }
    const float* kp = g_kw + bc * 9;
    float w0 = kp[0], w1 = kp[1], w2 = kp[2],
          w3 = kp[3], w4 = kp[4], w5 = kp[5],
          w6 = kp[6], w7 = kp[7], w8 = kp[8];
    float sc = g2[ch] * rsqrtf(v2[ch] + EPS);
    float bi = bt2[ch] - m2[ch] * sc;
    __syncthreads();
    __half2* yout2 = reinterpret_cast<__half2*>(g_y2h + (size_t)bc * HW);
    for (int i = threadIdx.x; i < HW / 2; i += 256) {
        int r = i / 28, c = (i - r * 28) * 2;
        const float* r0 = &t[r * TS + c];
        const float* r1 = r0 + TS;
        const float* r2 = r1 + TS;
        float a0 = r0[0], a1 = r0[1], a2 = r0[2], a3 = r0[3];
        float b0 = r1[0], b1 = r1[1], b2 = r1[2], b3 = r1[3];
        float c0 = r2[0], c1 = r2[1], c2 = r2[2], c3 = r2[3];
        float s0 = a0 * w0 + a1 * w1 + a2 * w2
                 + b0 * w3 + b1 * w4 + b2 * w5
                 + c0 * w6 + c1 * w7 + c2 * w8;
        float s1 = a1 * w0 + a2 * w1 + a3 * w2
                 + b1 * w3 + b2 * w4 + b3 * w5
                 + c1 * w6 + c2 * w7 + c3 * w8;
        s0 = fminf(fmaxf(s0 * sc + bi, 0.0f), 6.0f);
        s1 = fminf(fmaxf(s1 * sc + bi, 0.0f), 6.0f);
        yout2[i] = __floats2half2_rn(s0, s1);
    }
}

// ---------------- project GEMM (fp16 mma, fp32 accum, sw pipelined) ----------------
__global__ __launch_bounds__(256) void k_proj(const float* __restrict__ x,
        float* __restrict__ out,
        const float* __restrict__ g3, const float* __restrict__ bt3,
        const float* __restrict__ m3, const float* __restrict__ v3) {
    const int b = blockIdx.y, n0 = blockIdx.x * 128;
    __shared__ __align__(16) __half As[96 * ASTRIDE];   // [m][k]
    __shared__ __align__(16) __half Bs[128 * ASTRIDE];  // [n][k]
    const int tid = threadIdx.x, lane = tid & 31, wid = tid >> 5;
    const int wm = wid >> 2, wn = wid & 3;
    const int gID = lane >> 2, tig = lane & 3;
    float acc[3][4][4];
    #pragma unroll
    for (int i = 0; i < 3; i++)
        #pragma unroll
        for (int j = 0; j < 4; j++)
            #pragma unroll
            for (int q = 0; q < 4; q++) acc[i][j][q] = 0.0f;

    const __half* Ag = g_w3h + (size_t)b * COUT * HID;  // [m=96][k]
    const __half* Bg = g_y2h + (size_t)b * HID * HW;    // [k][n]

    __half2 pa[6], pb[4][2];
    const __half2 hz = __floats2half2_rn(0.f, 0.f);

    auto load_chunk = [&](int k0) {
        #pragma unroll
        for (int j = 0; j < 6; j++) {
            int i = tid + j * 256;
            int row = i >> 4, cp = i & 15;
            pa[j] = *reinterpret_cast<const __half2*>(&Ag[(size_t)row * HID + k0 + 2 * cp]);
        }
        #pragma unroll
        for (int j = 0; j < 4; j++) {
            int i = tid + j * 256;
            int n2 = (i & 63) * 2, kp = i >> 6;
            int n = n0 + n2;
            if (n < HW) {
                pb[j][0] = *reinterpret_cast<const __half2*>(&Bg[(size_t)(k0 + 2 * kp) * HW + n]);
                pb[j][1] = *reinterpret_cast<const __half2*>(&Bg[(size_t)(k0 + 2 * kp + 1) * HW + n]);
            } else { pb[j][0] = hz; pb[j][1] = hz; }
        }
    };
    auto store_chunk = [&]() {
        #pragma unroll
        for (int j = 0; j < 6; j++) {
            int i = tid + j * 256;
            int row = i >> 4, cp = i & 15;
            *reinterpret_cast<__half2*>(&As[row * ASTRIDE + 2 * cp]) = pa[j];
        }
        #pragma unroll
        for (int j = 0; j < 4; j++) {
            int i = tid + j * 256;
            int n2 = (i & 63) * 2, kp = i >> 6;
            *reinterpret_cast<__half2*>(&Bs[n2 * ASTRIDE + 2 * kp]) =
                __halves2half2(__low2half(pb[j][0]), __low2half(pb[j][1]));
            *reinterpret_cast<__half2*>(&Bs[(n2 + 1) * ASTRIDE + 2 * kp]) =
                __halves2half2(__high2half(pb[j][0]), __high2half(pb[j][1]));
        }
    };

    load_chunk(0);
    for (int c = 0; c < HID / 32; c++) {
        store_chunk();
        __syncthreads();
        if (c < HID / 32 - 1) load_chunk((c + 1) * 32);
        #pragma unroll
        for (int ks = 0; ks < 2; ks++) {
            const int kb = ks * 16;
            uint32_t a[3][4], bb[4][2];
            #pragma unroll
            for (int mt = 0; mt < 3; mt++) {
                int row = wm * 48 + mt * 16 + gID;
                const __half* p0 = &As[row * ASTRIDE + kb + 2 * tig];
                const __half* p1 = &As[(row + 8) * ASTRIDE + kb + 2 * tig];
                a[mt][0] = h2bits(*reinterpret_cast<const __half2*>(p0));
                a[mt][1] = h2bits(*reinterpret_cast<const __half2*>(p1));
                a[mt][2] = h2bits(*reinterpret_cast<const __half2*>(p0 + 8));
                a[mt][3] = h2bits(*reinterpret_cast<const __half2*>(p1 + 8));
            }
            #pragma unroll
            for (int nt = 0; nt < 4; nt++) {
                int col = wn * 32 + nt * 8 + gID;
                const __half* p = &Bs[col * ASTRIDE + kb + 2 * tig];
                bb[nt][0] = h2bits(*reinterpret_cast<const __half2*>(p));
                bb[nt][1] = h2bits(*reinterpret_cast<const __half2*>(p + 8));
            }
            #pragma unroll
            for (int mt = 0; mt < 3; mt++)
                #pragma unroll
                for (int nt = 0; nt < 4; nt++)
                    mma_f16(acc[mt][nt], a[mt], bb[nt]);
        }
        __syncthreads();
    }

    const float* xb = x + (size_t)b * CIN * HW;
    float* ob = out + (size_t)b * COUT * HW;
    #pragma unroll
    for (int mt = 0; mt < 3; mt++) {
        #pragma unroll
        for (int h = 0; h < 2; h++) {
            int m = wm * 48 + mt * 16 + gID + h * 8;
            float sc = g3[m] * rsqrtf(v3[m] + EPS);
            float bi = bt3[m] - m3[m] * sc;
            #pragma unroll
            for (int nt = 0; nt < 4; nt++) {
                int n = n0 + wn * 32 + nt * 8 + tig * 2;
                if (n < HW) {
                    float2 xv = *reinterpret_cast<const float2*>(&xb[(size_t)m * HW + n]);
                    float v0 = acc[mt][nt][h * 2 + 0] * sc + bi + xv.x;
                    float v1c = acc[mt][nt][h * 2 + 1] * sc + bi + xv.y;
                    *reinterpret_cast<float2*>(&ob[(size_t)m * HW + n]) = make_float2(v0, v1c);
                }
            }
        }
    }
}

// ---------------- launcher ----------------
extern "C" void kernel_launch(void* const* d_in, const int* in_sizes, int n_in,
                              void* d_out, int out_size) {
    const float* x    = (const float*)d_in[0];
    const float* w_r1 = (const float*)d_in[1];
    const float* b_r1 = (const float*)d_in[2];
    const float* w1   = (const float*)d_in[3];
    const float* g1   = (const float*)d_in[4];
    const float* bt1  = (const float*)d_in[5];
    const float* m1   = (const float*)d_in[6];
    const float* v1   = (const float*)d_in[7];
    const float* w_r2 = (const float*)d_in[8];
    const float* b_r2 = (const float*)d_in[9];
    const float* w2   = (const float*)d_in[10];
    const float* g2   = (const float*)d_in[11];
    const float* bt2  = (const float*)d_in[12];
    const float* m2   = (const float*)d_in[13];
    const float* v2   = (const float*)d_in[14];
    const float* w3   = (const float*)d_in[15];
    const float* g3   = (const float*)d_in[16];
    const float* bt3  = (const float*)d_in[17];
    const float* m3   = (const float*)d_in[18];
    const float* v3   = (const float*)d_in[19];
    const float* w_r3 = (const float*)d_in[20];
    const float* b_r3 = (const float*)d_in[21];
    float* out = (float*)d_out;

    k_xpool<<<B_ * CIN, 256>>>(x);
    k_route1<<<1, 256>>>(w_r1, b_r1, w_r3, b_r3);
    k_mix<<<dim3(216, 2 * B_), 256>>>(w1, w3);
    k_expand<<<dim3(25, 6, B_), 256>>>(g1, bt1, m1, v1);
    k_route2<<<B_, 256>>>(w_r2, b_r2, w2);
    k_dw<<<B_ * HID, 256>>>(g2, bt2, m2, v2);
    k_proj<<<dim3(25, B_), 256>>>(x, out, g3, bt3, m3, v3);
}

// round 5
// speedup vs baseline: 4.6093x; 1.3443x over previous
#include <cuda_runtime.h>
#include <cuda_fp16.h>
#include <math.h>
#include <stdint.h>

#define B_    32
#define CIN   96
#define COUT  96
#define HID   576
#define E_    8
#define HW    3136
#define WD    56
#define EPS   1e-5f

#define AST 104                 // A smem stride (halves): 208B -> conflict-free ldmatrix
#define BST 136                 // B smem stride (halves): 272B -> conflict-free ldmatrix.trans
#define ASZ (96 * AST * 2)      // 19968 bytes
#define BSZ (96 * BST * 2)      // 26112 bytes

// ---------------- scratch (device globals; no allocation) ----------------
__device__ __half g_xh  [(size_t)B_*CIN*HW];
__device__ __half g_yh  [(size_t)B_*HID*HW];
__device__ __half g_y2h [(size_t)B_*HID*HW];
__device__ float  g_xpool[B_*CIN];
__device__ float  g_ypool[B_*HID];
__device__ float  g_r1  [B_*E_];
__device__ float  g_rblk[B_*E_];
__device__ __half g_w1h [(size_t)B_*HID*CIN];  // [b][m=HID][k=CIN]
__device__ __half g_w3h [(size_t)B_*COUT*HID]; // [b][m=COUT][k=HID]
__device__ float  g_kw  [B_*HID*9];

// ---------------- asm helpers ----------------
__device__ __forceinline__ void mma_f16(float d[4], const uint32_t a[4], uint32_t b0, uint32_t b1) {
    asm volatile(
        "mma.sync.aligned.m16n8k16.row.col.f32.f16.f16.f32 "
        "{%0,%1,%2,%3}, {%4,%5,%6,%7}, {%8,%9}, {%0,%1,%2,%3};"
        : "+f"(d[0]), "+f"(d[1]), "+f"(d[2]), "+f"(d[3])
        : "r"(a[0]), "r"(a[1]), "r"(a[2]), "r"(a[3]), "r"(b0), "r"(b1));
}
__device__ __forceinline__ uint32_t smem_u32(const void* p) {
    return (uint32_t)__cvta_generic_to_shared(p);
}
__device__ __forceinline__ void cp16(uint32_t dst, const void* src) {
    asm volatile("cp.async.cg.shared.global [%0], [%1], 16;" :: "r"(dst), "l"(src) : "memory");
}
__device__ __forceinline__ void cp16z(uint32_t dst, const void* src, int zf) {
    asm volatile("cp.async.cg.shared.global [%0], [%1], 16, %2;" :: "r"(dst), "l"(src), "r"(zf) : "memory");
}
__device__ __forceinline__ void cp_commit() { asm volatile("cp.async.commit_group;" ::: "memory"); }
__device__ __forceinline__ void cp_wait0()  { asm volatile("cp.async.wait_group 0;" ::: "memory"); }
__device__ __forceinline__ void ldsm_x4(uint32_t r[4], uint32_t addr) {
    asm volatile("ldmatrix.sync.aligned.m8n8.x4.shared.b16 {%0,%1,%2,%3}, [%4];"
        : "=r"(r[0]), "=r"(r[1]), "=r"(r[2]), "=r"(r[3]) : "r"(addr));
}
__device__ __forceinline__ void ldsm_x4_t(uint32_t r[4], uint32_t addr) {
    asm volatile("ldmatrix.sync.aligned.m8n8.x4.trans.shared.b16 {%0,%1,%2,%3}, [%4];"
        : "=r"(r[0]), "=r"(r[1]), "=r"(r[2]), "=r"(r[3]) : "r"(addr));
}

// ---------------- xpool + fp16 conversion of x ----------------
__global__ void k_xpool(const float* __restrict__ x) {
    int bc = blockIdx.x;
    const float4* p = reinterpret_cast<const float4*>(x + (size_t)bc * HW);
    __half2* xo = reinterpret_cast<__half2*>(g_xh + (size_t)bc * HW);
    float s = 0.0f;
    for (int i = threadIdx.x; i < HW / 4; i += 256) {
        float4 v = p[i];
        s += (v.x + v.y) + (v.z + v.w);
        xo[2 * i]     = __floats2half2_rn(v.x, v.y);
        xo[2 * i + 1] = __floats2half2_rn(v.z, v.w);
    }
    #pragma unroll
    for (int o = 16; o > 0; o >>= 1) s += __shfl_xor_sync(0xffffffffu, s, o);
    __shared__ float sm[8];
    if ((threadIdx.x & 31) == 0) sm[threadIdx.x >> 5] = s;
    __syncthreads();
    if (threadIdx.x == 0) {
        float t = 0.0f;
        #pragma unroll
        for (int w = 0; w < 8; w++) t += sm[w];
        g_xpool[bc] = t * (1.0f / HW);
    }
}

// ---------------- routers for expand + block (also zeros ypool) ----------------
__global__ void k_route1(const float* __restrict__ wr1, const float* __restrict__ br1,
                         const float* __restrict__ wr3, const float* __restrict__ br3) {
    for (int i = threadIdx.x; i < B_ * HID; i += 256) g_ypool[i] = 0.0f;
    int t = threadIdx.x;
    int b = t >> 3, e = t & 7;
    const float* xp = g_xpool + b * CIN;
    float s1 = br1[e], s3 = br3[e];
    #pragma unroll 4
    for (int c = 0; c < CIN; c++) {
        float xv = xp[c];
        s1 += xv * wr1[e * CIN + c];
        s3 += xv * wr3[e * CIN + c];
    }
    g_r1[t]   = 1.0f / (1.0f + expf(-s1));
    g_rblk[t] = 1.0f / (1.0f + expf(-s3));
}

// ---------------- merged mix -> fp16 weights, [m][k] ----------------
__global__ void k_mix(const float* __restrict__ w1, const float* __restrict__ w3) {
    int bw = blockIdx.y;
    int b = bw & 31;
    int i = blockIdx.x * 256 + threadIdx.x;
    if (i >= HID * CIN) return;
    if (bw < B_) {
        const float* r = g_r1 + b * E_;
        float s = 0.0f;
        #pragma unroll
        for (int e = 0; e < E_; e++) s += r[e] * w1[(size_t)e * HID * CIN + i];
        g_w1h[(size_t)b * HID * CIN + i] = __float2half_rn(s);
    } else {
        const float* r = g_rblk + b * E_;
        float s = 0.0f;
        #pragma unroll
        for (int e = 0; e < E_; e++) s += r[e] * w3[(size_t)e * COUT * HID + i];
        g_w3h[(size_t)b * COUT * HID + i] = __float2half_rn(s);
    }
}

// ---------------- router2 + depthwise kernel mixing ----------------
__global__ void k_route2(const float* __restrict__ wr2, const float* __restrict__ br2,
                         const float* __restrict__ w2) {
    int b = blockIdx.x;
    __shared__ float rs[E_];
    int w = threadIdx.x >> 5, lane = threadIdx.x & 31;
    {
        const float* yp = g_ypool + b * HID;
        float s = 0.0f;
        for (int c = lane; c < HID; c += 32) s += yp[c] * wr2[w * HID + c];
        #pragma unroll
        for (int o = 16; o > 0; o >>= 1) s += __shfl_xor_sync(0xffffffffu, s, o);
        if (lane == 0) rs[w] = 1.0f / (1.0f + expf(-(s * (1.0f / HW) + br2[w])));
    }
    __syncthreads();
    for (int i = threadIdx.x; i < HID * 9; i += 256) {
        float s = 0.0f;
        #pragma unroll
        for (int e = 0; e < E_; e++) s += rs[e] * w2[(size_t)e * HID * 9 + i];
        g_kw[b * HID * 9 + i] = s;
    }
}

// ---------------- expand GEMM: cp.async + ldmatrix, A resident, 5 n-tiles/block ----
// y[b,m,n] = BN1/ReLU6( sum_k w1h[b,m,k] * xh[b,k,n] ), fused ypool reduction.
__global__ __launch_bounds__(256) void k_expand(
        const float* __restrict__ g1, const float* __restrict__ bt1,
        const float* __restrict__ m1, const float* __restrict__ v1) {
    extern __shared__ __align__(16) char smem[];
    const int b = blockIdx.z, m0 = blockIdx.y * 96;
    const uint32_t As_u = smem_u32(smem);
    const int tid = threadIdx.x, lane = tid & 31, wid = tid >> 5;
    const int wm = wid >> 2, wn = wid & 3;
    const int gID = lane >> 2, tig = lane & 3;
    const int grp = lane >> 3, rw = lane & 7;

    const __half* Ag = g_w1h + ((size_t)b * HID + m0) * CIN;
    const __half* Bg = g_xh + (size_t)b * CIN * HW;

    // stage A (whole 96x96) once
    for (int i = tid; i < 1152; i += 256) {
        int row = i / 12, seg = i % 12;
        cp16(As_u + (row * AST + seg * 8) * 2, Ag + (size_t)row * CIN + seg * 8);
    }
    // stage B tile 0
    {
        int n0 = blockIdx.x * 5 * 128;
        for (int i = tid; i < 1536; i += 256) {
            int row = i >> 4, seg = i & 15;
            int n = n0 + seg * 8;
            cp16z(As_u + ASZ + (row * BST + seg * 8) * 2,
                  Bg + (size_t)row * HW + (n < HW ? n : 0), (n < HW) ? 16 : 0);
        }
    }
    cp_commit();

    // BN constants per thread-row
    float scr[3][2], bir[3][2];
    #pragma unroll
    for (int mt = 0; mt < 3; mt++)
        #pragma unroll
        for (int h = 0; h < 2; h++) {
            int m = m0 + wm * 48 + mt * 16 + gID + h * 8;
            float sc = g1[m] * rsqrtf(v1[m] + EPS);
            scr[mt][h] = sc;
            bir[mt][h] = bt1[m] - m1[m] * sc;
        }
    float ysum[3][2] = {};
    __half* yb = g_yh + (size_t)b * HID * HW;

    for (int t = 0; t < 5; t++) {
        cp_wait0();
        __syncthreads();
        if (t < 4) {
            uint32_t bu = As_u + ASZ + ((t + 1) & 1) * BSZ;
            int n0 = (blockIdx.x * 5 + t + 1) * 128;
            for (int i = tid; i < 1536; i += 256) {
                int row = i >> 4, seg = i & 15;
                int n = n0 + seg * 8;
                cp16z(bu + (row * BST + seg * 8) * 2,
                      Bg + (size_t)row * HW + (n < HW ? n : 0), (n < HW) ? 16 : 0);
            }
            cp_commit();
        }
        const uint32_t Bs_u = As_u + ASZ + (t & 1) * BSZ;
        float acc[3][4][4] = {};
        #pragma unroll
        for (int kc = 0; kc < 6; kc++) {
            uint32_t a[3][4];
            #pragma unroll
            for (int mt = 0; mt < 3; mt++)
                ldsm_x4(a[mt], As_u + ((wm * 48 + mt * 16 + (grp & 1) * 8 + rw) * AST
                                        + kc * 16 + (grp >> 1) * 8) * 2);
            uint32_t bf[2][4];
            #pragma unroll
            for (int nb = 0; nb < 2; nb++)
                ldsm_x4_t(bf[nb], Bs_u + ((kc * 16 + (grp & 1) * 8 + rw) * BST
                                           + wn * 32 + nb * 16 + (grp >> 1) * 8) * 2);
            #pragma unroll
            for (int mt = 0; mt < 3; mt++) {
                mma_f16(acc[mt][0], a[mt], bf[0][0], bf[0][1]);
                mma_f16(acc[mt][1], a[mt], bf[0][2], bf[0][3]);
                mma_f16(acc[mt][2], a[mt], bf[1][0], bf[1][1]);
                mma_f16(acc[mt][3], a[mt], bf[1][2], bf[1][3]);
            }
        }
        // epilogue for tile t
        int n0 = (blockIdx.x * 5 + t) * 128;
        #pragma unroll
        for (int mt = 0; mt < 3; mt++) {
            #pragma unroll
            for (int h = 0; h < 2; h++) {
                int m = m0 + wm * 48 + mt * 16 + gID + h * 8;
                float sc = scr[mt][h], bi = bir[mt][h];
                #pragma unroll
                for (int nt = 0; nt < 4; nt++) {
                    int n = n0 + wn * 32 + nt * 8 + tig * 2;
                    if (n < HW) {
                        float v0 = fminf(fmaxf(acc[mt][nt][h * 2 + 0] * sc + bi, 0.0f), 6.0f);
                        float v1c = fminf(fmaxf(acc[mt][nt][h * 2 + 1] * sc + bi, 0.0f), 6.0f);
                        *reinterpret_cast<__half2*>(&yb[(size_t)m * HW + n]) = __floats2half2_rn(v0, v1c);
                        ysum[mt][h] += v0 + v1c;
                    }
                }
            }
        }
    }
    // ypool: reduce over tig lanes, one atomic per row per warp
    #pragma unroll
    for (int mt = 0; mt < 3; mt++)
        #pragma unroll
        for (int h = 0; h < 2; h++) {
            float s = ysum[mt][h];
            s += __shfl_xor_sync(0xffffffffu, s, 1);
            s += __shfl_xor_sync(0xffffffffu, s, 2);
            if (tig == 0)
                atomicAdd(&g_ypool[b * HID + m0 + wm * 48 + mt * 16 + gID + h * 8], s);
        }
}

// ---------------- depthwise 3x3 + BN2 + ReLU6 ----------------
#define TS 60
__global__ void k_dw(const float* __restrict__ g2, const float* __restrict__ bt2,
                     const float* __restrict__ m2, const float* __restrict__ v2) {
    int bc = blockIdx.x;
    int ch = bc % HID;
    __shared__ float t[58 * TS];
    const __half2* yin2 = reinterpret_cast<const __half2*>(g_yh + (size_t)bc * HW);
    for (int i = threadIdx.x; i < HW / 2; i += 256) {
        int r = i / 28, c = (i - r * 28) * 2;
        float2 v = __half22float2(yin2[i]);
        float* dst = &t[(r + 1) * TS + c + 1];
        dst[0] = v.x; dst[1] = v.y;
    }
    for (int i = threadIdx.x; i < 228; i += 256) {
        int idx;
        if (i < 58)       idx = i;
        else if (i < 116) idx = 57 * TS + (i - 58);
        else if (i < 172) idx = (i - 115) * TS;
        else              idx = (i - 171) * TS + 57;
        t[idx] = 0.0f;
    }
    const float* kp = g_kw + bc * 9;
    float w0 = kp[0], w1 = kp[1], w2 = kp[2],
          w3 = kp[3], w4 = kp[4], w5 = kp[5],
          w6 = kp[6], w7 = kp[7], w8 = kp[8];
    float sc = g2[ch] * rsqrtf(v2[ch] + EPS);
    float bi = bt2[ch] - m2[ch] * sc;
    __syncthreads();
    __half2* yout2 = reinterpret_cast<__half2*>(g_y2h + (size_t)bc * HW);
    for (int i = threadIdx.x; i < HW / 2; i += 256) {
        int r = i / 28, c = (i - r * 28) * 2;
        const float* r0 = &t[r * TS + c];
        const float* r1 = r0 + TS;
        const float* r2 = r1 + TS;
        float a0 = r0[0], a1 = r0[1], a2 = r0[2], a3 = r0[3];
        float b0 = r1[0], b1 = r1[1], b2 = r1[2], b3 = r1[3];
        float c0 = r2[0], c1 = r2[1], c2 = r2[2], c3 = r2[3];
        float s0 = a0 * w0 + a1 * w1 + a2 * w2
                 + b0 * w3 + b1 * w4 + b2 * w5
                 + c0 * w6 + c1 * w7 + c2 * w8;
        float s1 = a1 * w0 + a2 * w1 + a3 * w2
                 + b1 * w3 + b2 * w4 + b3 * w5
                 + c1 * w6 + c2 * w7 + c3 * w8;
        s0 = fminf(fmaxf(s0 * sc + bi, 0.0f), 6.0f);
        s1 = fminf(fmaxf(s1 * sc + bi, 0.0f), 6.0f);
        yout2[i] = __floats2half2_rn(s0, s1);
    }
}

// ---------------- project GEMM: cp.async + ldmatrix, K-chunks of 96 -------------
// out[b,m,n] = BN3( sum_k w3h[b,m,k] * y2h[b,k,n] ) + x[b,m,n]
__global__ __launch_bounds__(256) void k_proj(const float* __restrict__ x,
        float* __restrict__ out,
        const float* __restrict__ g3, const float* __restrict__ bt3,
        const float* __restrict__ m3, const float* __restrict__ v3) {
    extern __shared__ __align__(16) char smem[];
    const int b = blockIdx.y, n0 = blockIdx.x * 128;
    const uint32_t A_u = smem_u32(smem);
    const uint32_t B_u = A_u + 2 * ASZ;
    const int tid = threadIdx.x, lane = tid & 31, wid = tid >> 5;
    const int wm = wid >> 2, wn = wid & 3;
    const int gID = lane >> 2, tig = lane & 3;
    const int grp = lane >> 3, rw = lane & 7;

    const __half* Ag = g_w3h + (size_t)b * COUT * HID;
    const __half* Bg = g_y2h + (size_t)b * HID * HW;

    auto stage = [&](int c) {
        uint32_t au = A_u + (c & 1) * ASZ;
        for (int i = tid; i < 1152; i += 256) {
            int row = i / 12, seg = i % 12;
            cp16(au + (row * AST + seg * 8) * 2, Ag + (size_t)row * HID + c * 96 + seg * 8);
        }
        uint32_t bu = B_u + (c & 1) * BSZ;
        for (int i = tid; i < 1536; i += 256) {
            int row = i >> 4, seg = i & 15;
            int n = n0 + seg * 8;
            cp16z(bu + (row * BST + seg * 8) * 2,
                  Bg + (size_t)(c * 96 + row) * HW + (n < HW ? n : 0), (n < HW) ? 16 : 0);
        }
    };

    stage(0);
    cp_commit();
    float acc[3][4][4] = {};
    for (int c = 0; c < 6; c++) {
        cp_wait0();
        __syncthreads();
        if (c < 5) { stage(c + 1); cp_commit(); }
        const uint32_t au = A_u + (c & 1) * ASZ;
        const uint32_t bu = B_u + (c & 1) * BSZ;
        #pragma unroll
        for (int kc = 0; kc < 6; kc++) {
            uint32_t a[3][4];
            #pragma unroll
            for (int mt = 0; mt < 3; mt++)
                ldsm_x4(a[mt], au + ((wm * 48 + mt * 16 + (grp & 1) * 8 + rw) * AST
                                      + kc * 16 + (grp >> 1) * 8) * 2);
            uint32_t bf[2][4];
            #pragma unroll
            for (int nb = 0; nb < 2; nb++)
                ldsm_x4_t(bf[nb], bu + ((kc * 16 + (grp & 1) * 8 + rw) * BST
                                         + wn * 32 + nb * 16 + (grp >> 1) * 8) * 2);
            #pragma unroll
            for (int mt = 0; mt < 3; mt++) {
                mma_f16(acc[mt][0], a[mt], bf[0][0], bf[0][1]);
                mma_f16(acc[mt][1], a[mt], bf[0][2], bf[0][3]);
                mma_f16(acc[mt][2], a[mt], bf[1][0], bf[1][1]);
                mma_f16(acc[mt][3], a[mt], bf[1][2], bf[1][3]);
            }
        }
    }

    const float* xb = x + (size_t)b * CIN * HW;
    float* ob = out + (size_t)b * COUT * HW;
    #pragma unroll
    for (int mt = 0; mt < 3; mt++) {
        #pragma unroll
        for (int h = 0; h < 2; h++) {
            int m = wm * 48 + mt * 16 + gID + h * 8;
            float sc = g3[m] * rsqrtf(v3[m] + EPS);
            float bi = bt3[m] - m3[m] * sc;
            #pragma unroll
            for (int nt = 0; nt < 4; nt++) {
                int n = n0 + wn * 32 + nt * 8 + tig * 2;
                if (n < HW) {
                    float2 xv = *reinterpret_cast<const float2*>(&xb[(size_t)m * HW + n]);
                    float v0 = acc[mt][nt][h * 2 + 0] * sc + bi + xv.x;
                    float v1c = acc[mt][nt][h * 2 + 1] * sc + bi + xv.y;
                    *reinterpret_cast<float2*>(&ob[(size_t)m * HW + n]) = make_float2(v0, v1c);
                }
            }
        }
    }
}

// ---------------- launcher ----------------
extern "C" void kernel_launch(void* const* d_in, const int* in_sizes, int n_in,
                              void* d_out, int out_size) {
    const float* x    = (const float*)d_in[0];
    const float* w_r1 = (const float*)d_in[1];
    const float* b_r1 = (const float*)d_in[2];
    const float* w1   = (const float*)d_in[3];
    const float* g1   = (const float*)d_in[4];
    const float* bt1  = (const float*)d_in[5];
    const float* m1   = (const float*)d_in[6];
    const float* v1   = (const float*)d_in[7];
    const float* w_r2 = (const float*)d_in[8];
    const float* b_r2 = (const float*)d_in[9];
    const float* w2   = (const float*)d_in[10];
    const float* g2   = (const float*)d_in[11];
    const float* bt2  = (const float*)d_in[12];
    const float* v2   = (const float*)d_in[14];
    const float* m2   = (const float*)d_in[13];
    const float* w3   = (const float*)d_in[15];
    const float* g3   = (const float*)d_in[16];
    const float* bt3  = (const float*)d_in[17];
    const float* m3   = (const float*)d_in[18];
    const float* v3   = (const float*)d_in[19];
    const float* w_r3 = (const float*)d_in[20];
    const float* b_r3 = (const float*)d_in[21];
    float* out = (float*)d_out;

    static int attr_done = 0;
    if (!attr_done) {
        cudaFuncSetAttribute(k_expand, cudaFuncAttributeMaxDynamicSharedMemorySize,
                             ASZ + 2 * BSZ);
        cudaFuncSetAttribute(k_proj, cudaFuncAttributeMaxDynamicSharedMemorySize,
                             2 * ASZ + 2 * BSZ);
        attr_done = 1;
    }

    k_xpool<<<B_ * CIN, 256>>>(x);
    k_route1<<<1, 256>>>(w_r1, b_r1, w_r3, b_r3);
    k_mix<<<dim3(216, 2 * B_), 256>>>(w1, w3);
    k_expand<<<dim3(5, 6, B_), 256, ASZ + 2 * BSZ>>>(g1, bt1, m1, v1);
    k_route2<<<B_, 256>>>(w_r2, b_r2, w2);
    k_dw<<<B_ * HID, 256>>>(g2, bt2, m2, v2);
    k_proj<<<dim3(25, B_), 256, 2 * ASZ + 2 * BSZ>>>(x, out, g3, bt3, m3, v3);
}

// round 7
// speedup vs baseline: 5.4245x; 1.1769x over previous
#include <cuda_runtime.h>
#include <cuda_fp16.h>
#include <math.h>
#include <stdint.h>

#define B_    32
#define CIN   96
#define COUT  96
#define HID   576
#define E_    8
#define HW    3136
#define WD    56
#define EPS   1e-5f

#define AST 104                 // A smem stride (halves)
#define BST 136                 // B smem stride (halves)
#define ASZ (96 * AST * 2)
#define BSZ (96 * BST * 2)

// ---------------- scratch (device globals; no allocation) ----------------
__device__ __half g_xh  [(size_t)B_*CIN*HW];
__device__ __half g_yh  [(size_t)B_*HID*HW];
__device__ __half g_y2h [(size_t)B_*HID*HW];
__device__ float  g_xpool[B_*CIN];
__device__ float  g_ypool[B_*HID];
__device__ float  g_r1  [B_*E_];
__device__ float  g_rblk[B_*E_];
__device__ __half g_w1h [(size_t)B_*HID*CIN];  // [b][m=HID][k=CIN]
__device__ __half g_w3h [(size_t)B_*COUT*HID]; // [b][m=COUT][k=HID]
__device__ float  g_kw  [B_*HID*9];

// ---------------- asm helpers ----------------
__device__ __forceinline__ void mma_f16(float d[4], const uint32_t a[4], uint32_t b0, uint32_t b1) {
    asm volatile(
        "mma.sync.aligned.m16n8k16.row.col.f32.f16.f16.f32 "
        "{%0,%1,%2,%3}, {%4,%5,%6,%7}, {%8,%9}, {%0,%1,%2,%3};"
        : "+f"(d[0]), "+f"(d[1]), "+f"(d[2]), "+f"(d[3])
        : "r"(a[0]), "r"(a[1]), "r"(a[2]), "r"(a[3]), "r"(b0), "r"(b1));
}
__device__ __forceinline__ uint32_t smem_u32(const void* p) {
    return (uint32_t)__cvta_generic_to_shared(p);
}
__device__ __forceinline__ void cp16(uint32_t dst, const void* src) {
    asm volatile("cp.async.cg.shared.global [%0], [%1], 16;" :: "r"(dst), "l"(src) : "memory");
}
__device__ __forceinline__ void cp16z(uint32_t dst, const void* src, int zf) {
    asm volatile("cp.async.cg.shared.global [%0], [%1], 16, %2;" :: "r"(dst), "l"(src), "r"(zf) : "memory");
}
__device__ __forceinline__ void cp_commit() { asm volatile("cp.async.commit_group;" ::: "memory"); }
__device__ __forceinline__ void cp_wait0()  { asm volatile("cp.async.wait_group 0;" ::: "memory"); }
__device__ __forceinline__ void ldsm_x4(uint32_t r[4], uint32_t addr) {
    asm volatile("ldmatrix.sync.aligned.m8n8.x4.shared.b16 {%0,%1,%2,%3}, [%4];"
        : "=r"(r[0]), "=r"(r[1]), "=r"(r[2]), "=r"(r[3]) : "r"(addr));
}
__device__ __forceinline__ void ldsm_x4_t(uint32_t r[4], uint32_t addr) {
    asm volatile("ldmatrix.sync.aligned.m8n8.x4.trans.shared.b16 {%0,%1,%2,%3}, [%4];"
        : "=r"(r[0]), "=r"(r[1]), "=r"(r[2]), "=r"(r[3]) : "r"(addr));
}

// ---------------- xpool + fp16 conversion of x ----------------
__global__ void k_xpool(const float* __restrict__ x) {
    int bc = blockIdx.x;
    const float4* p = reinterpret_cast<const float4*>(x + (size_t)bc * HW);
    __half2* xo = reinterpret_cast<__half2*>(g_xh + (size_t)bc * HW);
    float s = 0.0f;
    for (int i = threadIdx.x; i < HW / 4; i += 256) {
        float4 v = p[i];
        s += (v.x + v.y) + (v.z + v.w);
        xo[2 * i]     = __floats2half2_rn(v.x, v.y);
        xo[2 * i + 1] = __floats2half2_rn(v.z, v.w);
    }
    #pragma unroll
    for (int o = 16; o > 0; o >>= 1) s += __shfl_xor_sync(0xffffffffu, s, o);
    __shared__ float sm[8];
    if ((threadIdx.x & 31) == 0) sm[threadIdx.x >> 5] = s;
    __syncthreads();
    if (threadIdx.x == 0) {
        float t = 0.0f;
        #pragma unroll
        for (int w = 0; w < 8; w++) t += sm[w];
        g_xpool[bc] = t * (1.0f / HW);
    }
}

// ---------------- routers for expand + block (also zeros ypool) ----------------
__global__ void k_route1(const float* __restrict__ wr1, const float* __restrict__ br1,
                         const float* __restrict__ wr3, const float* __restrict__ br3) {
    for (int i = threadIdx.x; i < B_ * HID; i += 256) g_ypool[i] = 0.0f;
    int t = threadIdx.x;
    int b = t >> 3, e = t & 7;
    const float* xp = g_xpool + b * CIN;
    float s1 = br1[e], s3 = br3[e];
    #pragma unroll 4
    for (int c = 0; c < CIN; c++) {
        float xv = xp[c];
        s1 += xv * wr1[e * CIN + c];
        s3 += xv * wr3[e * CIN + c];
    }
    g_r1[t]   = 1.0f / (1.0f + expf(-s1));
    g_rblk[t] = 1.0f / (1.0f + expf(-s3));
}

// ---------------- mix: load w once, loop all 32 batches ----------------
__global__ void k_mix(const float* __restrict__ w1, const float* __restrict__ w3) {
    const int i = blockIdx.x * 256 + threadIdx.x;      // 0..55295
    const int sel = blockIdx.y;                        // 0: w1, 1: w3
    __shared__ float rsh[B_ * E_];
    rsh[threadIdx.x] = sel ? g_rblk[threadIdx.x] : g_r1[threadIdx.x];
    __syncthreads();
    if (i >= HID * CIN) return;
    const float* w = sel ? w3 : w1;
    __half* o = sel ? g_w3h : g_w1h;
    float we[E_];
    #pragma unroll
    for (int e = 0; e < E_; e++) we[e] = w[(size_t)e * HID * CIN + i];
    #pragma unroll 4
    for (int b = 0; b < B_; b++) {
        const float* r = &rsh[b * E_];
        float s = 0.0f;
        #pragma unroll
        for (int e = 0; e < E_; e++) s += r[e] * we[e];
        o[(size_t)b * HID * CIN + i] = __float2half_rn(s);
    }
}

// ---------------- router2 + depthwise kernel mixing ----------------
__global__ void k_route2(const float* __restrict__ wr2, const float* __restrict__ br2,
                         const float* __restrict__ w2) {
    int b = blockIdx.x;
    __shared__ float rs[E_];
    int w = threadIdx.x >> 5, lane = threadIdx.x & 31;
    {
        const float* yp = g_ypool + b * HID;
        float s = 0.0f;
        for (int c = lane; c < HID; c += 32) s += yp[c] * wr2[w * HID + c];
        #pragma unroll
        for (int o = 16; o > 0; o >>= 1) s += __shfl_xor_sync(0xffffffffu, s, o);
        if (lane == 0) rs[w] = 1.0f / (1.0f + expf(-(s * (1.0f / HW) + br2[w])));
    }
    __syncthreads();
    for (int i = threadIdx.x; i < HID * 9; i += 256) {
        float s = 0.0f;
        #pragma unroll
        for (int e = 0; e < E_; e++) s += rs[e] * w2[(size_t)e * HID * 9 + i];
        g_kw[b * HID * 9 + i] = s;
    }
}

// ---------------- expand GEMM: cp.async + ldmatrix, A resident, 5 n-tiles/block ----
__global__ __launch_bounds__(256) void k_expand(
        const float* __restrict__ g1, const float* __restrict__ bt1,
        const float* __restrict__ m1, const float* __restrict__ v1) {
    extern __shared__ __align__(16) char smem[];
    const int b = blockIdx.z, m0 = blockIdx.y * 96;
    const uint32_t As_u = smem_u32(smem);
    const int tid = threadIdx.x, lane = tid & 31, wid = tid >> 5;
    const int wm = wid >> 2, wn = wid & 3;
    const int gID = lane >> 2, tig = lane & 3;
    const int grp = lane >> 3, rw = lane & 7;

    const __half* Ag = g_w1h + ((size_t)b * HID + m0) * CIN;
    const __half* Bg = g_xh + (size_t)b * CIN * HW;

    for (int i = tid; i < 1152; i += 256) {
        int row = i / 12, seg = i % 12;
        cp16(As_u + (row * AST + seg * 8) * 2, Ag + (size_t)row * CIN + seg * 8);
    }
    {
        int n0 = blockIdx.x * 5 * 128;
        for (int i = tid; i < 1536; i += 256) {
            int row = i >> 4, seg = i & 15;
            int n = n0 + seg * 8;
            cp16z(As_u + ASZ + (row * BST + seg * 8) * 2,
                  Bg + (size_t)row * HW + (n < HW ? n : 0), (n < HW) ? 16 : 0);
        }
    }
    cp_commit();

    float scr[3][2], bir[3][2];
    #pragma unroll
    for (int mt = 0; mt < 3; mt++)
        #pragma unroll
        for (int h = 0; h < 2; h++) {
            int m = m0 + wm * 48 + mt * 16 + gID + h * 8;
            float sc = g1[m] * rsqrtf(v1[m] + EPS);
            scr[mt][h] = sc;
            bir[mt][h] = bt1[m] - m1[m] * sc;
        }
    float ysum[3][2] = {};
    __half* yb = g_yh + (size_t)b * HID * HW;

    for (int t = 0; t < 5; t++) {
        cp_wait0();
        __syncthreads();
        if (t < 4) {
            uint32_t bu = As_u + ASZ + ((t + 1) & 1) * BSZ;
            int n0 = (blockIdx.x * 5 + t + 1) * 128;
            for (int i = tid; i < 1536; i += 256) {
                int row = i >> 4, seg = i & 15;
                int n = n0 + seg * 8;
                cp16z(bu + (row * BST + seg * 8) * 2,
                      Bg + (size_t)row * HW + (n < HW ? n : 0), (n < HW) ? 16 : 0);
            }
            cp_commit();
        }
        const uint32_t Bs_u = As_u + ASZ + (t & 1) * BSZ;
        float acc[3][4][4] = {};
        #pragma unroll
        for (int kc = 0; kc < 6; kc++) {
            uint32_t a[3][4];
            #pragma unroll
            for (int mt = 0; mt < 3; mt++)
                ldsm_x4(a[mt], As_u + ((wm * 48 + mt * 16 + (grp & 1) * 8 + rw) * AST
                                        + kc * 16 + (grp >> 1) * 8) * 2);
            uint32_t bf[2][4];
            #pragma unroll
            for (int nb = 0; nb < 2; nb++)
                ldsm_x4_t(bf[nb], Bs_u + ((kc * 16 + (grp & 1) * 8 + rw) * BST
                                           + wn * 32 + nb * 16 + (grp >> 1) * 8) * 2);
            #pragma unroll
            for (int mt = 0; mt < 3; mt++) {
                mma_f16(acc[mt][0], a[mt], bf[0][0], bf[0][1]);
                mma_f16(acc[mt][1], a[mt], bf[0][2], bf[0][3]);
                mma_f16(acc[mt][2], a[mt], bf[1][0], bf[1][1]);
                mma_f16(acc[mt][3], a[mt], bf[1][2], bf[1][3]);
            }
        }
        int n0 = (blockIdx.x * 5 + t) * 128;
        #pragma unroll
        for (int mt = 0; mt < 3; mt++) {
            #pragma unroll
            for (int h = 0; h < 2; h++) {
                int m = m0 + wm * 48 + mt * 16 + gID + h * 8;
                float sc = scr[mt][h], bi = bir[mt][h];
                #pragma unroll
                for (int nt = 0; nt < 4; nt++) {
                    int n = n0 + wn * 32 + nt * 8 + tig * 2;
                    if (n < HW) {
                        float v0 = fminf(fmaxf(acc[mt][nt][h * 2 + 0] * sc + bi, 0.0f), 6.0f);
                        float v1c = fminf(fmaxf(acc[mt][nt][h * 2 + 1] * sc + bi, 0.0f), 6.0f);
                        *reinterpret_cast<__half2*>(&yb[(size_t)m * HW + n]) = __floats2half2_rn(v0, v1c);
                        ysum[mt][h] += v0 + v1c;
                    }
                }
            }
        }
    }
    #pragma unroll
    for (int mt = 0; mt < 3; mt++)
        #pragma unroll
        for (int h = 0; h < 2; h++) {
            float s = ysum[mt][h];
            s += __shfl_xor_sync(0xffffffffu, s, 1);
            s += __shfl_xor_sync(0xffffffffu, s, 2);
            if (tig == 0)
                atomicAdd(&g_ypool[b * HID + m0 + wm * 48 + mt * 16 + gID + h * 8], s);
        }
}

// ---------------- depthwise 3x3 + BN2 + ReLU6 (smem-free, direct global) --------
// 224 threads = 56 rows x 4 col-segments of 14. Predicated aligned half2 loads.
__global__ __launch_bounds__(224) void k_dw(
        const float* __restrict__ g2, const float* __restrict__ bt2,
        const float* __restrict__ m2, const float* __restrict__ v2) {
    const int bc = blockIdx.x;             // b*HID + ch
    const int ch = bc % HID;
    const int t = threadIdx.x;
    const int r = t >> 2, seg = t & 3;
    const int c0 = seg * 14;
    const int o = c0 - 2;                  // window cols [o, o+18)

    const __half* yrow = g_yh + (size_t)bc * HW;
    const float* kp = g_kw + bc * 9;
    const float kw[9] = {kp[0], kp[1], kp[2], kp[3], kp[4], kp[5], kp[6], kp[7], kp[8]};
    const float sc = g2[ch] * rsqrtf(v2[ch] + EPS);
    const float bi = bt2[ch] - m2[ch] * sc;

    float acc[14] = {};
    #pragma unroll
    for (int dr = 0; dr < 3; dr++) {
        int rr = r + dr - 1;
        float v[18];
        if (rr >= 0 && rr < WD) {
            const __half* p = yrow + rr * WD;
            #pragma unroll
            for (int i = 0; i < 9; i++) {
                int col = o + 2 * i;
                if (col >= 0 && col < WD) {
                    float2 h = __half22float2(*reinterpret_cast<const __half2*>(p + col));
                    v[2 * i] = h.x; v[2 * i + 1] = h.y;
                } else { v[2 * i] = 0.0f; v[2 * i + 1] = 0.0f; }
            }
        } else {
            #pragma unroll
            for (int i = 0; i < 18; i++) v[i] = 0.0f;
        }
        const float w0 = kw[3 * dr], w1 = kw[3 * dr + 1], w2 = kw[3 * dr + 2];
        #pragma unroll
        for (int j = 0; j < 14; j++)
            acc[j] += v[j + 1] * w0 + v[j + 2] * w1 + v[j + 3] * w2;
    }

    __half2* out2 = reinterpret_cast<__half2*>(g_y2h + (size_t)bc * HW + r * WD + c0);
    #pragma unroll
    for (int j = 0; j < 7; j++) {
        float s0 = fminf(fmaxf(acc[2 * j]     * sc + bi, 0.0f), 6.0f);
        float s1 = fminf(fmaxf(acc[2 * j + 1] * sc + bi, 0.0f), 6.0f);
        out2[j] = __floats2half2_rn(s0, s1);
    }
}

// ---------------- project GEMM: cp.async + ldmatrix, K-chunks of 96 -------------
__global__ __launch_bounds__(256) void k_proj(const float* __restrict__ x,
        float* __restrict__ out,
        const float* __restrict__ g3, const float* __restrict__ bt3,
        const float* __restrict__ m3, const float* __restrict__ v3) {
    extern __shared__ __align__(16) char smem[];
    const int b = blockIdx.y, n0 = blockIdx.x * 128;
    const uint32_t A_u = smem_u32(smem);
    const uint32_t B_u = A_u + 2 * ASZ;
    const int tid = threadIdx.x, lane = tid & 31, wid = tid >> 5;
    const int wm = wid >> 2, wn = wid & 3;
    const int gID = lane >> 2, tig = lane & 3;
    const int grp = lane >> 3, rw = lane & 7;

    const __half* Ag = g_w3h + (size_t)b * COUT * HID;
    const __half* Bg = g_y2h + (size_t)b * HID * HW;

    auto stage = [&](int c) {
        uint32_t au = A_u + (c & 1) * ASZ;
        for (int i = tid; i < 1152; i += 256) {
            int row = i / 12, seg = i % 12;
            cp16(au + (row * AST + seg * 8) * 2, Ag + (size_t)row * HID + c * 96 + seg * 8);
        }
        uint32_t bu = B_u + (c & 1) * BSZ;
        for (int i = tid; i < 1536; i += 256) {
            int row = i >> 4, seg = i & 15;
            int n = n0 + seg * 8;
            cp16z(bu + (row * BST + seg * 8) * 2,
                  Bg + (size_t)(c * 96 + row) * HW + (n < HW ? n : 0), (n < HW) ? 16 : 0);
        }
    };

    stage(0);
    cp_commit();
    float acc[3][4][4] = {};
    for (int c = 0; c < 6; c++) {
        cp_wait0();
        __syncthreads();
        if (c < 5) { stage(c + 1); cp_commit(); }
        const uint32_t au = A_u + (c & 1) * ASZ;
        const uint32_t bu = B_u + (c & 1) * BSZ;
        #pragma unroll
        for (int kc = 0; kc < 6; kc++) {
            uint32_t a[3][4];
            #pragma unroll
            for (int mt = 0; mt < 3; mt++)
                ldsm_x4(a[mt], au + ((wm * 48 + mt * 16 + (grp & 1) * 8 + rw) * AST
                                      + kc * 16 + (grp >> 1) * 8) * 2);
            uint32_t bf[2][4];
            #pragma unroll
            for (int nb = 0; nb < 2; nb++)
                ldsm_x4_t(bf[nb], bu + ((kc * 16 + (grp & 1) * 8 + rw) * BST
                                         + wn * 32 + nb * 16 + (grp >> 1) * 8) * 2);
            #pragma unroll
            for (int mt = 0; mt < 3; mt++) {
                mma_f16(acc[mt][0], a[mt], bf[0][0], bf[0][1]);
                mma_f16(acc[mt][1], a[mt], bf[0][2], bf[0][3]);
                mma_f16(acc[mt][2], a[mt], bf[1][0], bf[1][1]);
                mma_f16(acc[mt][3], a[mt], bf[1][2], bf[1][3]);
            }
        }
    }

    const float* xb = x + (size_t)b * CIN * HW;
    float* ob = out + (size_t)b * COUT * HW;
    #pragma unroll
    for (int mt = 0; mt < 3; mt++) {
        #pragma unroll
        for (int h = 0; h < 2; h++) {
            int m = wm * 48 + mt * 16 + gID + h * 8;
            float sc = g3[m] * rsqrtf(v3[m] + EPS);
            float bi = bt3[m] - m3[m] * sc;
            #pragma unroll
            for (int nt = 0; nt < 4; nt++) {
                int n = n0 + wn * 32 + nt * 8 + tig * 2;
                if (n < HW) {
                    float2 xv = *reinterpret_cast<const float2*>(&xb[(size_t)m * HW + n]);
                    float v0 = acc[mt][nt][h * 2 + 0] * sc + bi + xv.x;
                    float v1c = acc[mt][nt][h * 2 + 1] * sc + bi + xv.y;
                    *reinterpret_cast<float2*>(&ob[(size_t)m * HW + n]) = make_float2(v0, v1c);
                }
            }
        }
    }
}

// ---------------- launcher ----------------
extern "C" void kernel_launch(void* const* d_in, const int* in_sizes, int n_in,
                              void* d_out, int out_size) {
    const float* x    = (const float*)d_in[0];
    const float* w_r1 = (const float*)d_in[1];
    const float* b_r1 = (const float*)d_in[2];
    const float* w1   = (const float*)d_in[3];
    const float* g1   = (const float*)d_in[4];
    const float* bt1  = (const float*)d_in[5];
    const float* m1   = (const float*)d_in[6];
    const float* v1   = (const float*)d_in[7];
    const float* w_r2 = (const float*)d_in[8];
    const float* b_r2 = (const float*)d_in[9];
    const float* w2   = (const float*)d_in[10];
    const float* g2   = (const float*)d_in[11];
    const float* bt2  = (const float*)d_in[12];
    const float* m2   = (const float*)d_in[13];
    const float* v2   = (const float*)d_in[14];
    const float* w3   = (const float*)d_in[15];
    const float* g3   = (const float*)d_in[16];
    const float* bt3  = (const float*)d_in[17];
    const float* m3   = (const float*)d_in[18];
    const float* v3   = (const float*)d_in[19];
    const float* w_r3 = (const float*)d_in[20];
    const float* b_r3 = (const float*)d_in[21];
    float* out = (float*)d_out;

    static int attr_done = 0;
    if (!attr_done) {
        cudaFuncSetAttribute(k_expand, cudaFuncAttributeMaxDynamicSharedMemorySize,
                             ASZ + 2 * BSZ);
        cudaFuncSetAttribute(k_proj, cudaFuncAttributeMaxDynamicSharedMemorySize,
                             2 * ASZ + 2 * BSZ);
        attr_done = 1;
    }

    k_xpool<<<B_ * CIN, 256>>>(x);
    k_route1<<<1, 256>>>(w_r1, b_r1, w_r3, b_r3);
    k_mix<<<dim3(216, 2), 256>>>(w1, w3);
    k_expand<<<dim3(5, 6, B_), 256, ASZ + 2 * BSZ>>>(g1, bt1, m1, v1);
    k_route2<<<B_, 256>>>(w_r2, b_r2, w2);
    k_dw<<<B_ * HID, 224>>>(g2, bt2, m2, v2);
    k_proj<<<dim3(25, B_), 256, 2 * ASZ + 2 * BSZ>>>(x, out, g3, bt3, m3, v3);
}